// round 12
// baseline (speedup 1.0000x reference)
#include <cuda_runtime.h>
#include <cuda_fp16.h>
#include <math.h>

// Problem constants
#define B     64
#define S     128
#define E     512
#define H     512
#define A_DIM 256
#define V     8192
#define T     32
#define KX    1024   // H + E (out-proj input [h|ctx])
#define KC    1024   // per-step gates input [ctx|h]
#define G4    2048   // 4*H
#define KSPLIT 8
#define KCHUNK (KC / KSPLIT)   // 128
#define NB    128    // persistent grid size

// smem layout (words) for k_loop dynamic smem
#define WSTR  132                       // padded row stride (128 + 4)
#define OFF_BH 0
#define OFF_BL (128 * WSTR)
#define OFF_AH (2 * 128 * WSTR)
#define OFF_AL (OFF_AH + 64 * WSTR)
#define LOOP_SMEM_WORDS (OFF_AL + 64 * WSTR)   // 50688 words = 202752 B

// -------------------- scratch (device globals) -----------------------------
__device__ float    g_encproj[B * S * A_DIM];
__device__ unsigned g_WencT_hi[A_DIM * E];
__device__ unsigned g_WencT_lo[A_DIM * E];
__device__ unsigned g_Wf_hi[G4 * KC];        // [ctx | h] weights
__device__ unsigned g_Wf_lo[G4 * KC];
__device__ unsigned g_We_hi[G4 * H];         // emb weights
__device__ unsigned g_We_lo[G4 * H];
__device__ float    g_bf[G4];
__device__ float    g_xh[B * KC];            // [ctx | h_prev]
__device__ float    g_xe[T * B * H];         // gathered embeddings
__device__ float    g_embpart[T * B * G4];   // emb @ We^T, all steps
__device__ float    g_hcatall[T * B * KX];   // [h_t | ctx_t] all steps
__device__ float    g_c[B * H];
__device__ float    g_gpart[KSPLIT * B * G4];
__device__ float    g_dp2[2 * B * A_DIM];    // dp partials (rank-split over K)
__device__ float    g_scores[B * S];         // raw attention scores
__device__ unsigned g_bar_count = 0;
__device__ unsigned g_bar_phase = 0;

// -------------------- helpers ----------------------------------------------
__device__ __forceinline__ unsigned f2tf32(float x) {
    unsigned r;
    asm("cvt.rna.tf32.f32 %0, %1;" : "=r"(r) : "f"(x));
    return r;
}
__device__ __forceinline__ float tanh_fast(float x) {
    float y;
    asm("tanh.approx.f32 %0, %1;" : "=f"(y) : "f"(x));
    return y;
}
// packed-half tanh: two tanh per MUFU op
__device__ __forceinline__ unsigned tanh2_f16(float x0, float x1) {
    unsigned p, r;
    asm("cvt.rn.f16x2.f32 %0, %1, %2;" : "=r"(p) : "f"(x1), "f"(x0));
    asm("tanh.approx.f16x2 %0, %1;" : "=r"(r) : "r"(p));
    return r;
}
__device__ __forceinline__ float sigmoid_fast(float x) {
    return __fdividef(1.f, 1.f + __expf(-x));
}
__device__ __forceinline__ void mma_tf32(float* d, const unsigned* a, const unsigned* b) {
    asm("mma.sync.aligned.m16n8k8.row.col.f32.tf32.tf32.f32 "
        "{%0,%1,%2,%3}, {%4,%5,%6,%7}, {%8,%9}, {%0,%1,%2,%3};"
        : "+f"(d[0]), "+f"(d[1]), "+f"(d[2]), "+f"(d[3])
        : "r"(a[0]), "r"(a[1]), "r"(a[2]), "r"(a[3]), "r"(b[0]), "r"(b[1]));
}

#define CLUSTER_SYNC() do { \
    asm volatile("barrier.cluster.arrive.aligned;" ::: "memory"); \
    asm volatile("barrier.cluster.wait.aligned;" ::: "memory"); \
} while (0)

__device__ __forceinline__ void grid_barrier() {
    __syncthreads();
    if (threadIdx.x == 0) {
        __threadfence();
        unsigned gen = *((volatile unsigned*)&g_bar_phase);
        if (atomicAdd(&g_bar_count, 1u) == NB - 1) {
            *((volatile unsigned*)&g_bar_count) = 0;
            __threadfence();
            *((volatile unsigned*)&g_bar_phase) = gen + 1;
        } else {
            while (*((volatile unsigned*)&g_bar_phase) == gen) {}
        }
        __threadfence();
    }
    __syncthreads();
}

// weight-stationary gates MMA tile: gpart[kc] tile (64 x 128 @ n0), K-chunk kbase
__device__ __forceinline__ void gates_mma(unsigned* Ah, unsigned* Al,
                                          const unsigned* Bh, const unsigned* Bl,
                                          int kbase, int kc, int n0,
                                          int tid, int warp, int lane) {
    int wm = warp >> 2, wn = warp & 3;
    int qr = lane >> 2, qc = lane & 3;

    // stage A tile (64 x 128) -> hi/lo smem
    {
        int ar = tid >> 2;
        int acb = (tid & 3) * 32;
        const float* Ag = g_xh + ar * KC + kbase + acb;
        #pragma unroll
        for (int j = 0; j < 8; j++) {
            float4 v = *(const float4*)(Ag + j * 4);
            float a[4] = {v.x, v.y, v.z, v.w};
            #pragma unroll
            for (int i = 0; i < 4; i++) {
                unsigned hi = f2tf32(a[i]);
                Ah[ar * WSTR + acb + j * 4 + i] = hi;
                Al[ar * WSTR + acb + j * 4 + i] = f2tf32(a[i] - __uint_as_float(hi));
            }
        }
    }
    __syncthreads();

    float acc[2][4][4] = {};
    #pragma unroll
    for (int ks = 0; ks < KCHUNK; ks += 8) {
        unsigned ah[2][4], al2[2][4], bhf[4][2], blf[4][2];
        #pragma unroll
        for (int mt = 0; mt < 2; mt++) {
            int r = wm * 32 + mt * 16 + qr;
            int c = ks + qc;
            ah[mt][0] = Ah[r * WSTR + c];
            ah[mt][1] = Ah[(r + 8) * WSTR + c];
            ah[mt][2] = Ah[r * WSTR + c + 4];
            ah[mt][3] = Ah[(r + 8) * WSTR + c + 4];
            al2[mt][0] = Al[r * WSTR + c];
            al2[mt][1] = Al[(r + 8) * WSTR + c];
            al2[mt][2] = Al[r * WSTR + c + 4];
            al2[mt][3] = Al[(r + 8) * WSTR + c + 4];
        }
        #pragma unroll
        for (int nt = 0; nt < 4; nt++) {
            int n = wn * 32 + nt * 8 + qr;
            int c = ks + qc;
            bhf[nt][0] = Bh[n * WSTR + c];
            bhf[nt][1] = Bh[n * WSTR + c + 4];
            blf[nt][0] = Bl[n * WSTR + c];
            blf[nt][1] = Bl[n * WSTR + c + 4];
        }
        #pragma unroll
        for (int mt = 0; mt < 2; mt++)
            #pragma unroll
            for (int nt = 0; nt < 4; nt++) {
                mma_tf32(acc[mt][nt], ah[mt], bhf[nt]);
                mma_tf32(acc[mt][nt], ah[mt], blf[nt]);
                mma_tf32(acc[mt][nt], al2[mt], bhf[nt]);
            }
    }

    float* Cp = g_gpart + (size_t)kc * B * G4;
    #pragma unroll
    for (int mt = 0; mt < 2; mt++)
        #pragma unroll
        for (int nt = 0; nt < 4; nt++) {
            int col = n0 + wn * 32 + nt * 8 + qc * 2;
            #pragma unroll
            for (int half = 0; half < 2; half++) {
                int row = wm * 32 + mt * 16 + qr + half * 8;
                float2 v = {acc[mt][nt][half * 2 + 0],
                            acc[mt][nt][half * 2 + 1]};
                *(float2*)&Cp[(size_t)row * G4 + col] = v;
            }
        }
}

// -------------------- setup (incl. embedding gather) -----------------------
__global__ void k_prep(const float* __restrict__ W_enc,
                       const float* __restrict__ W_ih,
                       const float* __restrict__ W_hh,
                       const float* __restrict__ b_ih,
                       const float* __restrict__ b_hh,
                       const int* __restrict__ tgt,
                       const float* __restrict__ emb) {
    int stride = gridDim.x * blockDim.x;
    int tid0 = blockIdx.x * blockDim.x + threadIdx.x;
    for (int i = tid0; i < A_DIM * E; i += stride) {
        int a = i / E, e = i % E;
        float v = W_enc[e * A_DIM + a];
        unsigned hi = f2tf32(v);
        g_WencT_hi[i] = hi;
        g_WencT_lo[i] = f2tf32(v - __uint_as_float(hi));
    }
    for (int i = tid0; i < G4 * KC; i += stride) {
        int j = i / KC, k = i % KC;
        float v = (k < H) ? W_ih[j * KX + H + k] : W_hh[j * H + (k - H)];
        unsigned hi = f2tf32(v);
        g_Wf_hi[i] = hi;
        g_Wf_lo[i] = f2tf32(v - __uint_as_float(hi));
    }
    for (int i = tid0; i < G4 * H; i += stride) {
        int j = i / H, k = i % H;
        float v = W_ih[j * KX + k];
        unsigned hi = f2tf32(v);
        g_We_hi[i] = hi;
        g_We_lo[i] = f2tf32(v - __uint_as_float(hi));
    }
    for (int i = tid0; i < G4; i += stride) g_bf[i] = b_ih[i] + b_hh[i];
    for (int i = tid0; i < B * H; i += stride) {
        g_c[i] = 0.0f;
        int b = i / H, j = i % H;
        g_xh[b * KC + H + j] = 0.0f;   // h0 = 0
    }
    for (int i = tid0; i < T * B * H; i += stride) {
        int r = i >> 9, k = i & 511;
        int t = r >> 6, b = r & 63;
        int tok = (t == 0) ? 0 : tgt[b * T + t - 1];
        g_xe[i] = emb[(size_t)tok * H + k];
    }
}

// -------------------- split-TF32 tensor-core GEMM (standalone) -------------
#define MSTR 20
__global__ __launch_bounds__(256, 2)
void k_mma_split(const float* __restrict__ A, int lda,
                 const unsigned* __restrict__ Bhi,
                 const unsigned* __restrict__ Blo, int ldb,
                 float* __restrict__ C, int ldc, size_t czstride,
                 int kchunk) {
    __shared__ unsigned Ah[64 * MSTR], Al[64 * MSTR];
    __shared__ unsigned Bh[128 * MSTR], Bl[128 * MSTR];
    int tid = threadIdx.x;
    int lane = tid & 31, w = tid >> 5;
    int wm = w >> 2, wn = w & 3;
    int qr = lane >> 2, qc = lane & 3;
    int m0 = blockIdx.y * 64, n0 = blockIdx.x * 128;
    int kbase = blockIdx.z * kchunk;

    int ar = tid >> 2, ac = (tid & 3) * 4;
    const float* Ag = A + (size_t)(m0 + ar) * lda + kbase + ac;
    int br = tid >> 1, bc = (tid & 1) * 8;
    const unsigned* Bhg = Bhi + (size_t)(n0 + br) * ldb + kbase + bc;
    const unsigned* Blg = Blo + (size_t)(n0 + br) * ldb + kbase + bc;

    float acc[2][4][4] = {};
    int nk = kchunk >> 4;
    for (int kt = 0; kt < nk; kt++) {
        int koff = kt * 16;
        float4 av = *(const float4*)(Ag + koff);
        uint4 bh0 = *(const uint4*)(Bhg + koff);
        uint4 bh1 = *(const uint4*)(Bhg + koff + 4);
        uint4 bl0 = *(const uint4*)(Blg + koff);
        uint4 bl1 = *(const uint4*)(Blg + koff + 4);
        __syncthreads();
        {
            float a[4] = {av.x, av.y, av.z, av.w};
            #pragma unroll
            for (int i = 0; i < 4; i++) {
                unsigned hi = f2tf32(a[i]);
                Ah[ar * MSTR + ac + i] = hi;
                Al[ar * MSTR + ac + i] = f2tf32(a[i] - __uint_as_float(hi));
            }
            unsigned* bp = &Bh[br * MSTR + bc];
            bp[0] = bh0.x; bp[1] = bh0.y; bp[2] = bh0.z; bp[3] = bh0.w;
            bp[4] = bh1.x; bp[5] = bh1.y; bp[6] = bh1.z; bp[7] = bh1.w;
            unsigned* lp = &Bl[br * MSTR + bc];
            lp[0] = bl0.x; lp[1] = bl0.y; lp[2] = bl0.z; lp[3] = bl0.w;
            lp[4] = bl1.x; lp[5] = bl1.y; lp[6] = bl1.z; lp[7] = bl1.w;
        }
        __syncthreads();

        #pragma unroll
        for (int ks = 0; ks < 16; ks += 8) {
            unsigned ah[2][4], al[2][4], bhf[4][2], blf[4][2];
            #pragma unroll
            for (int mt = 0; mt < 2; mt++) {
                int r = wm * 32 + mt * 16 + qr;
                int c = ks + qc;
                ah[mt][0] = Ah[r * MSTR + c];
                ah[mt][1] = Ah[(r + 8) * MSTR + c];
                ah[mt][2] = Ah[r * MSTR + c + 4];
                ah[mt][3] = Ah[(r + 8) * MSTR + c + 4];
                al[mt][0] = Al[r * MSTR + c];
                al[mt][1] = Al[(r + 8) * MSTR + c];
                al[mt][2] = Al[r * MSTR + c + 4];
                al[mt][3] = Al[(r + 8) * MSTR + c + 4];
            }
            #pragma unroll
            for (int nt = 0; nt < 4; nt++) {
                int n = wn * 32 + nt * 8 + qr;
                int c = ks + qc;
                bhf[nt][0] = Bh[n * MSTR + c];
                bhf[nt][1] = Bh[n * MSTR + c + 4];
                blf[nt][0] = Bl[n * MSTR + c];
                blf[nt][1] = Bl[n * MSTR + c + 4];
            }
            #pragma unroll
            for (int mt = 0; mt < 2; mt++)
                #pragma unroll
                for (int nt = 0; nt < 4; nt++) {
                    mma_tf32(acc[mt][nt], ah[mt], bhf[nt]);
                    mma_tf32(acc[mt][nt], ah[mt], blf[nt]);
                    mma_tf32(acc[mt][nt], al[mt], bhf[nt]);
                }
        }
    }

    float* Cp = C + (size_t)blockIdx.z * czstride;
    #pragma unroll
    for (int mt = 0; mt < 2; mt++)
        #pragma unroll
        for (int nt = 0; nt < 4; nt++) {
            int col = n0 + wn * 32 + nt * 8 + qc * 2;
            #pragma unroll
            for (int half = 0; half < 2; half++) {
                int row = m0 + wm * 32 + mt * 16 + qr + half * 8;
                float2 v = {acc[mt][nt][half * 2 + 0],
                            acc[mt][nt][half * 2 + 1]};
                *(float2*)&Cp[(size_t)row * ldc + col] = v;
            }
        }
}

// -------------------- persistent step loop (cluster-split attention) --------
// 64 clusters of 2 CTAs; cluster c handles batch b=c with work rank-split.
__global__ __launch_bounds__(256, 1) __cluster_dims__(2, 1, 1)
void k_loop(const float* __restrict__ enc, const float* __restrict__ W_dec,
            const float* __restrict__ b_att, const float* __restrict__ v_att) {
    extern __shared__ __align__(16) unsigned dyn[];
    int tid = threadIdx.x;
    int lane = tid & 31, warp = tid >> 5;
    int kc = blockIdx.x >> 4;
    int n0 = (blockIdx.x & 15) * 128;
    int kbase = kc * KCHUNK;
    int b = blockIdx.x >> 1;       // batch for attention duty
    int rank = blockIdx.x & 1;     // role within the pair

    unsigned* Bh = dyn + OFF_BH;
    unsigned* Bl = dyn + OFF_BL;
    unsigned* Ah = dyn + OFF_AH;
    unsigned* Al = dyn + OFF_AL;

    // attention scratch aliases the A-staging region (disjoint in time)
    float* sh_h  = (float*)(dyn + OFF_AH);   // 256 (this rank's h slice)
    float* sh_dp = sh_h + 256;               // 256
    float* sh_v  = sh_dp + 256;              // 256
    float* sh_sc = sh_v + 256;               // 128

    // one-time: pin this block's gates weight tile in smem
    {
        int r = tid >> 1;
        int cb = (tid & 1) * 64;
        const unsigned* hg = g_Wf_hi + (size_t)(n0 + r) * KC + kbase + cb;
        const unsigned* lg = g_Wf_lo + (size_t)(n0 + r) * KC + kbase + cb;
        #pragma unroll
        for (int j = 0; j < 16; j++) {
            uint4 hv = *(const uint4*)(hg + j * 4);
            uint4 lv = *(const uint4*)(lg + j * 4);
            unsigned* hp = &Bh[r * WSTR + cb + j * 4];
            unsigned* lp = &Bl[r * WSTR + cb + j * 4];
            hp[0] = hv.x; hp[1] = hv.y; hp[2] = hv.z; hp[3] = hv.w;
            lp[0] = lv.x; lp[1] = lv.y; lp[2] = lv.z; lp[3] = lv.w;
        }
    }
    __syncthreads();

    for (int t = 0; t <= T; t++) {
        // ---- P1: LSTM(t-1), rank-split over j (256 each) ----
        if (t > 0) {
            int j = rank * 256 + tid;
            const float* ep = &g_embpart[(size_t)((t - 1) * B + b) * G4];
            float gi = g_bf[j] + ep[j];
            float gf = g_bf[j + H] + ep[j + H];
            float gg = g_bf[j + 2 * H] + ep[j + 2 * H];
            float go = g_bf[j + 3 * H] + ep[j + 3 * H];
            #pragma unroll
            for (int p = 0; p < KSPLIT; p++) {
                const float* gp = &g_gpart[(size_t)(p * B + b) * G4];
                gi += gp[j];         gf += gp[j + H];
                gg += gp[j + 2 * H]; go += gp[j + 3 * H];
            }
            float c = g_c[b * H + j];
            float cn = sigmoid_fast(gf) * c + sigmoid_fast(gi) * tanh_fast(gg);
            float hn = sigmoid_fast(go) * tanh_fast(cn);
            g_c[b * H + j] = cn;
            sh_h[tid] = hn;
            g_xh[b * KC + H + j] = hn;
            g_hcatall[(size_t)((t - 1) * B + b) * KX + j] = hn;
        } else {
            sh_h[tid] = 0.f;
        }
        if (t == T) return;
        __syncthreads();

        // ---- P2: dp partial over this rank's h slice (K-split) ----
        {
            const float* wd = W_dec + (size_t)(rank * 256) * A_DIM + tid;
            float a0 = 0.f, a1 = 0.f, a2 = 0.f, a3 = 0.f;
            #pragma unroll 4
            for (int e = 0; e < 256; e += 4) {
                a0 += sh_h[e]     * wd[(size_t)(e)     * A_DIM];
                a1 += sh_h[e + 1] * wd[(size_t)(e + 1) * A_DIM];
                a2 += sh_h[e + 2] * wd[(size_t)(e + 2) * A_DIM];
                a3 += sh_h[e + 3] * wd[(size_t)(e + 3) * A_DIM];
            }
            g_dp2[(rank * B + b) * A_DIM + tid] = (a0 + a1) + (a2 + a3);
        }
        CLUSTER_SYNC();   // release dp partials to the pair

        // ---- P3: scores for s in [rank*64, rank*64+64) (f16x2 tanh) ----
        {
            sh_dp[tid] = b_att[tid]
                       + g_dp2[(0 * B + b) * A_DIM + tid]
                       + g_dp2[(1 * B + b) * A_DIM + tid];
            sh_v[tid] = v_att[tid];
            __syncthreads();
            for (int si = warp; si < 64; si += 8) {
                int s = rank * 64 + si;
                const float* ep2 = &g_encproj[((size_t)b * S + s) * A_DIM];
                float acc = 0.f;
                #pragma unroll
                for (int a = lane; a < A_DIM; a += 64) {
                    float x0 = ep2[a] + sh_dp[a];
                    float x1 = ep2[a + 32] + sh_dp[a + 32];
                    unsigned th = tanh2_f16(x0, x1);
                    __half2 h2 = *reinterpret_cast<__half2*>(&th);
                    acc += __low2float(h2) * sh_v[a]
                         + __high2float(h2) * sh_v[a + 32];
                }
                #pragma unroll
                for (int o = 16; o; o >>= 1)
                    acc += __shfl_xor_sync(0xffffffffu, acc, o);
                if (lane == 0) g_scores[b * S + s] = acc;
            }
        }
        CLUSTER_SYNC();   // release scores to the pair

        // ---- P4: softmax (redundant in both CTAs) + ctx (e-split) ----
        {
            if (tid < S) sh_sc[tid] = g_scores[b * S + tid];
            __syncthreads();
            if (warp == 0) {
                float v0 = sh_sc[lane], v1 = sh_sc[lane + 32];
                float v2 = sh_sc[lane + 64], v3 = sh_sc[lane + 96];
                float m = fmaxf(fmaxf(v0, v1), fmaxf(v2, v3));
                #pragma unroll
                for (int o = 16; o; o >>= 1)
                    m = fmaxf(m, __shfl_xor_sync(0xffffffffu, m, o));
                float e0 = __expf(v0 - m), e1 = __expf(v1 - m);
                float e2 = __expf(v2 - m), e3 = __expf(v3 - m);
                float sum = e0 + e1 + e2 + e3;
                #pragma unroll
                for (int o = 16; o; o >>= 1)
                    sum += __shfl_xor_sync(0xffffffffu, sum, o);
                float inv = __fdividef(1.f, sum);
                sh_sc[lane] = e0 * inv;        sh_sc[lane + 32] = e1 * inv;
                sh_sc[lane + 64] = e2 * inv;   sh_sc[lane + 96] = e3 * inv;
            }
            __syncthreads();

            // ctx: this rank handles e in [rank*256, rank*256+256), 1 per thread
            int e = rank * 256 + tid;
            const float* eb = &enc[((size_t)b * S) * E + e];
            float a0 = 0.f, a1 = 0.f, a2 = 0.f, a3 = 0.f;
            #pragma unroll 4
            for (int s = 0; s < S; s += 4) {
                a0 += sh_sc[s]     * eb[(size_t)(s)     * E];
                a1 += sh_sc[s + 1] * eb[(size_t)(s + 1) * E];
                a2 += sh_sc[s + 2] * eb[(size_t)(s + 2) * E];
                a3 += sh_sc[s + 3] * eb[(size_t)(s + 3) * E];
            }
            float acc = (a0 + a1) + (a2 + a3);
            g_xh[b * KC + e] = acc;
            g_hcatall[(size_t)(t * B + b) * KX + H + e] = acc;
        }
        grid_barrier();

        // ---- P5: gates MMA (all 128 blocks, pinned tiles) ----
        gates_mma(Ah, Al, Bh, Bl, kbase, kc, n0, tid, warp, lane);
        grid_barrier();
    }
}

// -------------------- TF32 tensor-core output GEMM (OBK=32) ----------------
#define OBK 32
#define SSTR 36
__global__ __launch_bounds__(256, 2)
void k_out_mma(const float* __restrict__ Bw, const float* __restrict__ bias,
               float* __restrict__ out) {
    __shared__ unsigned As[128 * SSTR];
    __shared__ unsigned Bs[128 * SSTR];
    int tid = threadIdx.x;
    int lane = tid & 31, w = tid >> 5;
    int wm = w >> 2, wn = w & 3;
    int m0 = blockIdx.y * 128, n0 = blockIdx.x * 128;

    int lrow = tid >> 1;
    int lcol = (tid & 1) * 16;
    const float* Ag = &g_hcatall[(size_t)(m0 + lrow) * KX + lcol];
    const float* Bg = Bw + (size_t)(n0 + lrow) * KX + lcol;

    float acc[4][4][4] = {};
    int qr = lane >> 2, qc = lane & 3;

    for (int k0 = 0; k0 < KX; k0 += OBK) {
        float4 a0 = *(const float4*)(Ag + k0);
        float4 a1 = *(const float4*)(Ag + k0 + 4);
        float4 a2 = *(const float4*)(Ag + k0 + 8);
        float4 a3 = *(const float4*)(Ag + k0 + 12);
        float4 b0 = *(const float4*)(Bg + k0);
        float4 b1 = *(const float4*)(Bg + k0 + 4);
        float4 b2 = *(const float4*)(Bg + k0 + 8);
        float4 b3 = *(const float4*)(Bg + k0 + 12);
        __syncthreads();
        {
            unsigned* ap = &As[lrow * SSTR + lcol];
            ap[0]  = f2tf32(a0.x); ap[1]  = f2tf32(a0.y);
            ap[2]  = f2tf32(a0.z); ap[3]  = f2tf32(a0.w);
            ap[4]  = f2tf32(a1.x); ap[5]  = f2tf32(a1.y);
            ap[6]  = f2tf32(a1.z); ap[7]  = f2tf32(a1.w);
            ap[8]  = f2tf32(a2.x); ap[9]  = f2tf32(a2.y);
            ap[10] = f2tf32(a2.z); ap[11] = f2tf32(a2.w);
            ap[12] = f2tf32(a3.x); ap[13] = f2tf32(a3.y);
            ap[14] = f2tf32(a3.z); ap[15] = f2tf32(a3.w);
            unsigned* bp = &Bs[lrow * SSTR + lcol];
            bp[0]  = f2tf32(b0.x); bp[1]  = f2tf32(b0.y);
            bp[2]  = f2tf32(b0.z); bp[3]  = f2tf32(b0.w);
            bp[4]  = f2tf32(b1.x); bp[5]  = f2tf32(b1.y);
            bp[6]  = f2tf32(b1.z); bp[7]  = f2tf32(b1.w);
            bp[8]  = f2tf32(b2.x); bp[9]  = f2tf32(b2.y);
            bp[10] = f2tf32(b2.z); bp[11] = f2tf32(b2.w);
            bp[12] = f2tf32(b3.x); bp[13] = f2tf32(b3.y);
            bp[14] = f2tf32(b3.z); bp[15] = f2tf32(b3.w);
        }
        __syncthreads();

        #pragma unroll
        for (int ks = 0; ks < OBK; ks += 8) {
            unsigned afr[4][4], bfr[4][2];
            #pragma unroll
            for (int mt = 0; mt < 4; mt++) {
                int r = wm * 64 + mt * 16 + qr;
                int c = ks + qc;
                afr[mt][0] = As[r * SSTR + c];
                afr[mt][1] = As[(r + 8) * SSTR + c];
                afr[mt][2] = As[r * SSTR + c + 4];
                afr[mt][3] = As[(r + 8) * SSTR + c + 4];
            }
            #pragma unroll
            for (int nt = 0; nt < 4; nt++) {
                int n = wn * 32 + nt * 8 + qr;
                int c = ks + qc;
                bfr[nt][0] = Bs[n * SSTR + c];
                bfr[nt][1] = Bs[n * SSTR + c + 4];
            }
            #pragma unroll
            for (int mt = 0; mt < 4; mt++)
                #pragma unroll
                for (int nt = 0; nt < 4; nt++)
                    mma_tf32(acc[mt][nt], afr[mt], bfr[nt]);
        }
    }

    #pragma unroll
    for (int mt = 0; mt < 4; mt++) {
        #pragma unroll
        for (int nt = 0; nt < 4; nt++) {
            int ncol = n0 + wn * 32 + nt * 8 + qc * 2;
            float bz0 = bias[ncol], bz1 = bias[ncol + 1];
            #pragma unroll
            for (int half = 0; half < 2; half++) {
                int r = m0 + wm * 64 + mt * 16 + qr + half * 8;
                int bidx = r & (B - 1);
                int tt = r >> 6;
                float* o = out + (size_t)bidx * T * V + (size_t)tt * V + ncol;
                float2 v = {acc[mt][nt][half * 2 + 0] + bz0,
                            acc[mt][nt][half * 2 + 1] + bz1};
                *(float2*)o = v;
            }
        }
    }
}

// -------------------- launch ------------------------------------------------
extern "C" void kernel_launch(void* const* d_in, const int* in_sizes, int n_in,
                              void* d_out, int out_size) {
    const float* enc   = (const float*)d_in[0];
    const int*   tgt   = (const int*)  d_in[1];
    const float* emb   = (const float*)d_in[2];
    const float* W_enc = (const float*)d_in[3];
    const float* W_dec = (const float*)d_in[4];
    const float* b_att = (const float*)d_in[5];
    const float* v_att = (const float*)d_in[6];
    const float* W_ih  = (const float*)d_in[7];
    const float* W_hh  = (const float*)d_in[8];
    const float* b_ih  = (const float*)d_in[9];
    const float* b_hh  = (const float*)d_in[10];
    const float* W_out = (const float*)d_in[11];
    const float* b_out = (const float*)d_in[12];
    float* out = (float*)d_out;

    float *p_encproj, *p_xe, *p_embpart;
    unsigned *p_WencT_hi, *p_WencT_lo, *p_We_hi, *p_We_lo;
    cudaGetSymbolAddress((void**)&p_encproj,  g_encproj);
    cudaGetSymbolAddress((void**)&p_xe,       g_xe);
    cudaGetSymbolAddress((void**)&p_embpart,  g_embpart);
    cudaGetSymbolAddress((void**)&p_WencT_hi, g_WencT_hi);
    cudaGetSymbolAddress((void**)&p_WencT_lo, g_WencT_lo);
    cudaGetSymbolAddress((void**)&p_We_hi,    g_We_hi);
    cudaGetSymbolAddress((void**)&p_We_lo,    g_We_lo);

    static bool attr_done = false;
    if (!attr_done) {
        cudaFuncSetAttribute(k_loop, cudaFuncAttributeMaxDynamicSharedMemorySize,
                             LOOP_SMEM_WORDS * 4);
        attr_done = true;
    }

    k_prep<<<512, 256>>>(W_enc, W_ih, W_hh, b_ih, b_hh, tgt, emb);

    // enc_proj[B*S, A] = enc @ W_enc (split-tf32)
    {
        dim3 grid(A_DIM / 128, (B * S) / 64, 1);
        k_mma_split<<<grid, 256>>>(enc, E, p_WencT_hi, p_WencT_lo, E,
                                   p_encproj, A_DIM, 0, E);
    }
    // embpart[T*B, G4] = xe @ We^T (split-tf32), once for all steps
    {
        dim3 grid(G4 / 128, (T * B) / 64, 1);
        k_mma_split<<<grid, 256>>>(p_xe, H, p_We_hi, p_We_lo, H,
                                   p_embpart, G4, 0, H);
    }

    // whole decode loop: persistent, cluster-paired attention, f16x2 tanh
    k_loop<<<NB, 256, LOOP_SMEM_WORDS * 4>>>(enc, W_dec, b_att, v_att);

    // output projection for all timesteps
    {
        dim3 grid(V / 128, (T * B) / 128);
        k_out_mma<<<grid, 256>>>(W_out, b_out, out);
    }
}

// round 13
// speedup vs baseline: 1.1082x; 1.1082x over previous
#include <cuda_runtime.h>
#include <math.h>

// Problem constants
#define B     64
#define S     128
#define E     512
#define H     512
#define A_DIM 256
#define V     8192
#define T     32
#define KX    1024
#define KC    1024
#define G4    2048
#define KSPLIT 8
#define KCHUNK (KC / KSPLIT)   // 128
#define NB    128
#define NT_LOOP 512            // threads per k_loop block

// smem layout (words) for k_loop dynamic smem
#define WSTR  132
#define OFF_BH 0
#define OFF_BL (128 * WSTR)
#define OFF_AH (2 * 128 * WSTR)
#define OFF_AL (OFF_AH + 64 * WSTR)
#define LOOP_SMEM_WORDS (OFF_AL + 64 * WSTR)   // 50688 words = 202752 B

// -------------------- scratch (device globals) -----------------------------
__device__ float    g_encproj[B * S * A_DIM];
__device__ unsigned g_WencT_hi[A_DIM * E];
__device__ unsigned g_WencT_lo[A_DIM * E];
__device__ unsigned g_Wf_hi[G4 * KC];
__device__ unsigned g_Wf_lo[G4 * KC];
__device__ unsigned g_We_hi[G4 * H];
__device__ unsigned g_We_lo[G4 * H];
__device__ float    g_bf[G4];
__device__ float    g_xh[B * KC];            // [ctx | h_prev]
__device__ float    g_xe[T * B * H];
__device__ float    g_embpart[T * B * G4];
__device__ float    g_hcatall[T * B * KX];
__device__ float    g_c[B * H];
__device__ float    g_gpart[KSPLIT * B * G4];
__device__ float    g_dp2[2 * B * A_DIM];
__device__ float    g_scores[B * S];
__device__ unsigned g_bar_count = 0;
__device__ unsigned g_bar_phase = 0;

// -------------------- helpers ----------------------------------------------
__device__ __forceinline__ unsigned f2tf32(float x) {
    unsigned r;
    asm("cvt.rna.tf32.f32 %0, %1;" : "=r"(r) : "f"(x));
    return r;
}
__device__ __forceinline__ float tanh_fast(float x) {
    float y;
    asm("tanh.approx.f32 %0, %1;" : "=f"(y) : "f"(x));
    return y;
}
__device__ __forceinline__ float sigmoid_fast(float x) {
    return __fdividef(1.f, 1.f + __expf(-x));
}
__device__ __forceinline__ void mma_tf32(float* d, const unsigned* a, const unsigned* b) {
    asm("mma.sync.aligned.m16n8k8.row.col.f32.tf32.tf32.f32 "
        "{%0,%1,%2,%3}, {%4,%5,%6,%7}, {%8,%9}, {%0,%1,%2,%3};"
        : "+f"(d[0]), "+f"(d[1]), "+f"(d[2]), "+f"(d[3])
        : "r"(a[0]), "r"(a[1]), "r"(a[2]), "r"(a[3]), "r"(b[0]), "r"(b[1]));
}

#define CLUSTER_SYNC() do { \
    asm volatile("barrier.cluster.arrive.aligned;" ::: "memory"); \
    asm volatile("barrier.cluster.wait.aligned;" ::: "memory"); \
} while (0)

__device__ __forceinline__ void grid_barrier() {
    __syncthreads();
    if (threadIdx.x == 0) {
        __threadfence();
        unsigned gen = *((volatile unsigned*)&g_bar_phase);
        if (atomicAdd(&g_bar_count, 1u) == NB - 1) {
            *((volatile unsigned*)&g_bar_count) = 0;
            __threadfence();
            *((volatile unsigned*)&g_bar_phase) = gen + 1;
        } else {
            while (*((volatile unsigned*)&g_bar_phase) == gen) {}
        }
        __threadfence();
    }
    __syncthreads();
}

// -------------------- setup (incl. embedding gather) -----------------------
__global__ void k_prep(const float* __restrict__ W_enc,
                       const float* __restrict__ W_ih,
                       const float* __restrict__ W_hh,
                       const float* __restrict__ b_ih,
                       const float* __restrict__ b_hh,
                       const int* __restrict__ tgt,
                       const float* __restrict__ emb) {
    int stride = gridDim.x * blockDim.x;
    int tid0 = blockIdx.x * blockDim.x + threadIdx.x;
    for (int i = tid0; i < A_DIM * E; i += stride) {
        int a = i / E, e = i % E;
        float v = W_enc[e * A_DIM + a];
        unsigned hi = f2tf32(v);
        g_WencT_hi[i] = hi;
        g_WencT_lo[i] = f2tf32(v - __uint_as_float(hi));
    }
    for (int i = tid0; i < G4 * KC; i += stride) {
        int j = i / KC, k = i % KC;
        float v = (k < H) ? W_ih[j * KX + H + k] : W_hh[j * H + (k - H)];
        unsigned hi = f2tf32(v);
        g_Wf_hi[i] = hi;
        g_Wf_lo[i] = f2tf32(v - __uint_as_float(hi));
    }
    for (int i = tid0; i < G4 * H; i += stride) {
        int j = i / H, k = i % H;
        float v = W_ih[j * KX + k];
        unsigned hi = f2tf32(v);
        g_We_hi[i] = hi;
        g_We_lo[i] = f2tf32(v - __uint_as_float(hi));
    }
    for (int i = tid0; i < G4; i += stride) g_bf[i] = b_ih[i] + b_hh[i];
    for (int i = tid0; i < B * H; i += stride) {
        g_c[i] = 0.0f;
        int b = i / H, j = i % H;
        g_xh[b * KC + H + j] = 0.0f;
    }
    for (int i = tid0; i < T * B * H; i += stride) {
        int r = i >> 9, k = i & 511;
        int t = r >> 6, b = r & 63;
        int tok = (t == 0) ? 0 : tgt[b * T + t - 1];
        g_xe[i] = emb[(size_t)tok * H + k];
    }
}

// -------------------- split-TF32 tensor-core GEMM (standalone) -------------
#define MSTR 20
__global__ __launch_bounds__(256, 2)
void k_mma_split(const float* __restrict__ A, int lda,
                 const unsigned* __restrict__ Bhi,
                 const unsigned* __restrict__ Blo, int ldb,
                 float* __restrict__ C, int ldc, size_t czstride,
                 int kchunk) {
    __shared__ unsigned Ah[64 * MSTR], Al[64 * MSTR];
    __shared__ unsigned Bh[128 * MSTR], Bl[128 * MSTR];
    int tid = threadIdx.x;
    int lane = tid & 31, w = tid >> 5;
    int wm = w >> 2, wn = w & 3;
    int qr = lane >> 2, qc = lane & 3;
    int m0 = blockIdx.y * 64, n0 = blockIdx.x * 128;
    int kbase = blockIdx.z * kchunk;

    int ar = tid >> 2, ac = (tid & 3) * 4;
    const float* Ag = A + (size_t)(m0 + ar) * lda + kbase + ac;
    int br = tid >> 1, bc = (tid & 1) * 8;
    const unsigned* Bhg = Bhi + (size_t)(n0 + br) * ldb + kbase + bc;
    const unsigned* Blg = Blo + (size_t)(n0 + br) * ldb + kbase + bc;

    float acc[2][4][4] = {};
    int nk = kchunk >> 4;
    for (int kt = 0; kt < nk; kt++) {
        int koff = kt * 16;
        float4 av = *(const float4*)(Ag + koff);
        uint4 bh0 = *(const uint4*)(Bhg + koff);
        uint4 bh1 = *(const uint4*)(Bhg + koff + 4);
        uint4 bl0 = *(const uint4*)(Blg + koff);
        uint4 bl1 = *(const uint4*)(Blg + koff + 4);
        __syncthreads();
        {
            float a[4] = {av.x, av.y, av.z, av.w};
            #pragma unroll
            for (int i = 0; i < 4; i++) {
                unsigned hi = f2tf32(a[i]);
                Ah[ar * MSTR + ac + i] = hi;
                Al[ar * MSTR + ac + i] = f2tf32(a[i] - __uint_as_float(hi));
            }
            unsigned* bp = &Bh[br * MSTR + bc];
            bp[0] = bh0.x; bp[1] = bh0.y; bp[2] = bh0.z; bp[3] = bh0.w;
            bp[4] = bh1.x; bp[5] = bh1.y; bp[6] = bh1.z; bp[7] = bh1.w;
            unsigned* lp = &Bl[br * MSTR + bc];
            lp[0] = bl0.x; lp[1] = bl0.y; lp[2] = bl0.z; lp[3] = bl0.w;
            lp[4] = bl1.x; lp[5] = bl1.y; lp[6] = bl1.z; lp[7] = bl1.w;
        }
        __syncthreads();

        #pragma unroll
        for (int ks = 0; ks < 16; ks += 8) {
            unsigned ah[2][4], al[2][4], bhf[4][2], blf[4][2];
            #pragma unroll
            for (int mt = 0; mt < 2; mt++) {
                int r = wm * 32 + mt * 16 + qr;
                int c = ks + qc;
                ah[mt][0] = Ah[r * MSTR + c];
                ah[mt][1] = Ah[(r + 8) * MSTR + c];
                ah[mt][2] = Ah[r * MSTR + c + 4];
                ah[mt][3] = Ah[(r + 8) * MSTR + c + 4];
                al[mt][0] = Al[r * MSTR + c];
                al[mt][1] = Al[(r + 8) * MSTR + c];
                al[mt][2] = Al[r * MSTR + c + 4];
                al[mt][3] = Al[(r + 8) * MSTR + c + 4];
            }
            #pragma unroll
            for (int nt = 0; nt < 4; nt++) {
                int n = wn * 32 + nt * 8 + qr;
                int c = ks + qc;
                bhf[nt][0] = Bh[n * MSTR + c];
                bhf[nt][1] = Bh[n * MSTR + c + 4];
                blf[nt][0] = Bl[n * MSTR + c];
                blf[nt][1] = Bl[n * MSTR + c + 4];
            }
            #pragma unroll
            for (int mt = 0; mt < 2; mt++)
                #pragma unroll
                for (int nt = 0; nt < 4; nt++) {
                    mma_tf32(acc[mt][nt], ah[mt], bhf[nt]);
                    mma_tf32(acc[mt][nt], ah[mt], blf[nt]);
                    mma_tf32(acc[mt][nt], al[mt], bhf[nt]);
                }
        }
    }

    float* Cp = C + (size_t)blockIdx.z * czstride;
    #pragma unroll
    for (int mt = 0; mt < 2; mt++)
        #pragma unroll
        for (int nt = 0; nt < 4; nt++) {
            int col = n0 + wn * 32 + nt * 8 + qc * 2;
            #pragma unroll
            for (int half = 0; half < 2; half++) {
                int row = m0 + wm * 32 + mt * 16 + qr + half * 8;
                float2 v = {acc[mt][nt][half * 2 + 0],
                            acc[mt][nt][half * 2 + 1]};
                *(float2*)&Cp[(size_t)row * ldc + col] = v;
            }
        }
}

// -------------------- persistent step loop (512 thr, 16-warp phases) --------
__global__ __launch_bounds__(NT_LOOP, 1) __cluster_dims__(2, 1, 1)
void k_loop(const float* __restrict__ enc, const float* __restrict__ W_dec,
            const float* __restrict__ b_att, const float* __restrict__ v_att) {
    extern __shared__ __align__(16) unsigned dyn[];
    int tid = threadIdx.x;
    int lane = tid & 31, warp = tid >> 5;
    int kc = blockIdx.x >> 4;
    int n0 = (blockIdx.x & 15) * 128;
    int kbase = kc * KCHUNK;
    int b = blockIdx.x >> 1;
    int rank = blockIdx.x & 1;
    int half_id = tid >> 8;          // 0 or 1
    int hid = tid & 255;             // 0..255

    unsigned* Bh = dyn + OFF_BH;
    unsigned* Bl = dyn + OFF_BL;
    unsigned* Ah = dyn + OFF_AH;
    unsigned* Al = dyn + OFF_AL;

    // attention scratch aliases Ah/Al staging (disjoint in time)
    float* sh_h   = (float*)(dyn + OFF_AH);  // 256
    float* sh_dp  = sh_h + 256;              // 256
    float* sh_v   = sh_dp + 256;             // 256
    float* sh_sc  = sh_v + 256;              // 128
    float* sh_tmp = sh_sc + 128;             // 512
    float* sh_red = sh_tmp + 512;            // 4*512 = 2048 (LSTM partials)

    // one-time: pin gates weight tile (512 threads)
    {
        int r = tid >> 2;                 // 0..127
        int cb = (tid & 3) * 32;          // 0,32,64,96
        const unsigned* hg = g_Wf_hi + (size_t)(n0 + r) * KC + kbase + cb;
        const unsigned* lg = g_Wf_lo + (size_t)(n0 + r) * KC + kbase + cb;
        #pragma unroll
        for (int j = 0; j < 8; j++) {
            uint4 hv = *(const uint4*)(hg + j * 4);
            uint4 lv = *(const uint4*)(lg + j * 4);
            unsigned* hp = &Bh[r * WSTR + cb + j * 4];
            unsigned* lp = &Bl[r * WSTR + cb + j * 4];
            hp[0] = hv.x; hp[1] = hv.y; hp[2] = hv.z; hp[3] = hv.w;
            lp[0] = lv.x; lp[1] = lv.y; lp[2] = lv.z; lp[3] = lv.w;
        }
    }
    __syncthreads();

    for (int t = 0; t <= T; t++) {
        // ---- P1: LSTM(t-1); j = rank*256+hid; partial-sum split over halves ----
        if (t > 0) {
            int j = rank * 256 + hid;
            float gi, gf, gg, go;
            if (half_id == 0) {
                const float* ep = &g_embpart[(size_t)((t - 1) * B + b) * G4];
                gi = g_bf[j] + ep[j];
                gf = g_bf[j + H] + ep[j + H];
                gg = g_bf[j + 2 * H] + ep[j + 2 * H];
                go = g_bf[j + 3 * H] + ep[j + 3 * H];
            } else {
                gi = gf = gg = go = 0.f;
            }
            #pragma unroll
            for (int p = half_id * 4; p < half_id * 4 + 4; p++) {
                const float* gp = &g_gpart[(size_t)(p * B + b) * G4];
                gi += gp[j];         gf += gp[j + H];
                gg += gp[j + 2 * H]; go += gp[j + 3 * H];
            }
            sh_red[0 * 512 + tid] = gi;
            sh_red[1 * 512 + tid] = gf;
            sh_red[2 * 512 + tid] = gg;
            sh_red[3 * 512 + tid] = go;
            __syncthreads();
            if (half_id == 0) {
                float fi = sh_red[0 * 512 + hid] + sh_red[0 * 512 + 256 + hid];
                float ff = sh_red[1 * 512 + hid] + sh_red[1 * 512 + 256 + hid];
                float fg = sh_red[2 * 512 + hid] + sh_red[2 * 512 + 256 + hid];
                float fo = sh_red[3 * 512 + hid] + sh_red[3 * 512 + 256 + hid];
                float c = g_c[b * H + j];
                float cn = sigmoid_fast(ff) * c + sigmoid_fast(fi) * tanh_fast(fg);
                float hn = sigmoid_fast(fo) * tanh_fast(cn);
                g_c[b * H + j] = cn;
                sh_h[hid] = hn;
                g_xh[b * KC + H + j] = hn;
                g_hcatall[(size_t)((t - 1) * B + b) * KX + j] = hn;
            }
        } else {
            if (half_id == 0) sh_h[hid] = 0.f;
        }
        if (t == T) return;
        __syncthreads();

        // ---- P2: dp partial; a = hid, e-range split over halves ----
        {
            const float* wd = W_dec + (size_t)(rank * 256 + half_id * 128) * A_DIM + hid;
            float a0 = 0.f, a1 = 0.f, a2 = 0.f, a3 = 0.f;
            const float* hh = sh_h + half_id * 128;
            #pragma unroll 4
            for (int e = 0; e < 128; e += 4) {
                a0 += hh[e]     * wd[(size_t)(e)     * A_DIM];
                a1 += hh[e + 1] * wd[(size_t)(e + 1) * A_DIM];
                a2 += hh[e + 2] * wd[(size_t)(e + 2) * A_DIM];
                a3 += hh[e + 3] * wd[(size_t)(e + 3) * A_DIM];
            }
            sh_tmp[tid] = (a0 + a1) + (a2 + a3);
            __syncthreads();
            if (half_id == 0)
                g_dp2[(rank * B + b) * A_DIM + hid] = sh_tmp[hid] + sh_tmp[hid + 256];
        }
        CLUSTER_SYNC();

        // ---- P3: scores; 16 warps, 4 s each ----
        {
            if (half_id == 0) {
                sh_dp[hid] = b_att[hid]
                           + g_dp2[(0 * B + b) * A_DIM + hid]
                           + g_dp2[(1 * B + b) * A_DIM + hid];
                sh_v[hid] = v_att[hid];
            }
            __syncthreads();
            for (int si = warp; si < 64; si += 16) {
                int s = rank * 64 + si;
                const float* ep2 = &g_encproj[((size_t)b * S + s) * A_DIM];
                float acc = 0.f;
                #pragma unroll
                for (int a = lane; a < A_DIM; a += 32)
                    acc += tanh_fast(ep2[a] + sh_dp[a]) * sh_v[a];
                #pragma unroll
                for (int o = 16; o; o >>= 1)
                    acc += __shfl_xor_sync(0xffffffffu, acc, o);
                if (lane == 0) g_scores[b * S + s] = acc;
            }
        }
        CLUSTER_SYNC();

        // ---- P4: softmax (warp 0) + ctx (e=hid slice, s-range split) ----
        {
            if (tid < S) sh_sc[tid] = g_scores[b * S + tid];
            __syncthreads();
            if (warp == 0) {
                float v0 = sh_sc[lane], v1 = sh_sc[lane + 32];
                float v2 = sh_sc[lane + 64], v3 = sh_sc[lane + 96];
                float m = fmaxf(fmaxf(v0, v1), fmaxf(v2, v3));
                #pragma unroll
                for (int o = 16; o; o >>= 1)
                    m = fmaxf(m, __shfl_xor_sync(0xffffffffu, m, o));
                float e0 = __expf(v0 - m), e1 = __expf(v1 - m);
                float e2 = __expf(v2 - m), e3 = __expf(v3 - m);
                float sum = e0 + e1 + e2 + e3;
                #pragma unroll
                for (int o = 16; o; o >>= 1)
                    sum += __shfl_xor_sync(0xffffffffu, sum, o);
                float inv = __fdividef(1.f, sum);
                sh_sc[lane] = e0 * inv;        sh_sc[lane + 32] = e1 * inv;
                sh_sc[lane + 64] = e2 * inv;   sh_sc[lane + 96] = e3 * inv;
            }
            __syncthreads();

            int e = rank * 256 + hid;
            const float* eb = &enc[((size_t)b * S + half_id * 64) * E + e];
            const float* sc = sh_sc + half_id * 64;
            float a0 = 0.f, a1 = 0.f, a2 = 0.f, a3 = 0.f;
            #pragma unroll 4
            for (int s = 0; s < 64; s += 4) {
                a0 += sc[s]     * eb[(size_t)(s)     * E];
                a1 += sc[s + 1] * eb[(size_t)(s + 1) * E];
                a2 += sc[s + 2] * eb[(size_t)(s + 2) * E];
                a3 += sc[s + 3] * eb[(size_t)(s + 3) * E];
            }
            sh_tmp[tid] = (a0 + a1) + (a2 + a3);
            __syncthreads();
            if (half_id == 0) {
                float acc = sh_tmp[hid] + sh_tmp[hid + 256];
                g_xh[b * KC + e] = acc;
                g_hcatall[(size_t)(t * B + b) * KX + H + e] = acc;
            }
        }
        grid_barrier();

        // ---- P5: gates MMA, 16 warps (warp tile 16 x 32) ----
        {
            int wm = warp >> 2, wn = warp & 3;     // 4 x 4 warp grid
            int qr = lane >> 2, qc = lane & 3;

            // stage A tile (64 x 128): 512 threads, 16 elems each
            {
                int ar = tid >> 3;                 // 0..63
                int acb = (tid & 7) * 16;          // 0..112
                const float* Ag = g_xh + ar * KC + kbase + acb;
                #pragma unroll
                for (int j = 0; j < 4; j++) {
                    float4 v = *(const float4*)(Ag + j * 4);
                    float a[4] = {v.x, v.y, v.z, v.w};
                    #pragma unroll
                    for (int i = 0; i < 4; i++) {
                        unsigned hi = f2tf32(a[i]);
                        Ah[ar * WSTR + acb + j * 4 + i] = hi;
                        Al[ar * WSTR + acb + j * 4 + i] =
                            f2tf32(a[i] - __uint_as_float(hi));
                    }
                }
            }
            __syncthreads();

            float acc[4][4] = {};
            #pragma unroll
            for (int ks = 0; ks < KCHUNK; ks += 8) {
                unsigned ah[4], al2[4], bhf[4][2], blf[4][2];
                int r = wm * 16 + qr;
                int c = ks + qc;
                ah[0] = Ah[r * WSTR + c];
                ah[1] = Ah[(r + 8) * WSTR + c];
                ah[2] = Ah[r * WSTR + c + 4];
                ah[3] = Ah[(r + 8) * WSTR + c + 4];
                al2[0] = Al[r * WSTR + c];
                al2[1] = Al[(r + 8) * WSTR + c];
                al2[2] = Al[r * WSTR + c + 4];
                al2[3] = Al[(r + 8) * WSTR + c + 4];
                #pragma unroll
                for (int nt = 0; nt < 4; nt++) {
                    int n = wn * 32 + nt * 8 + qr;
                    bhf[nt][0] = Bh[n * WSTR + c];
                    bhf[nt][1] = Bh[n * WSTR + c + 4];
                    blf[nt][0] = Bl[n * WSTR + c];
                    blf[nt][1] = Bl[n * WSTR + c + 4];
                }
                #pragma unroll
                for (int nt = 0; nt < 4; nt++) {
                    mma_tf32(acc[nt], ah, bhf[nt]);
                    mma_tf32(acc[nt], ah, blf[nt]);
                    mma_tf32(acc[nt], al2, bhf[nt]);
                }
            }

            float* Cp = g_gpart + (size_t)kc * B * G4;
            #pragma unroll
            for (int nt = 0; nt < 4; nt++) {
                int col = n0 + wn * 32 + nt * 8 + qc * 2;
                #pragma unroll
                for (int half = 0; half < 2; half++) {
                    int row = wm * 16 + qr + half * 8;
                    float2 v = {acc[nt][half * 2 + 0], acc[nt][half * 2 + 1]};
                    *(float2*)&Cp[(size_t)row * G4 + col] = v;
                }
            }
        }
        grid_barrier();
    }
}

// -------------------- TF32 tensor-core output GEMM (OBK=32) ----------------
#define OBK 32
#define SSTR 36
__global__ __launch_bounds__(256, 2)
void k_out_mma(const float* __restrict__ Bw, const float* __restrict__ bias,
               float* __restrict__ out) {
    __shared__ unsigned As[128 * SSTR];
    __shared__ unsigned Bs[128 * SSTR];
    int tid = threadIdx.x;
    int lane = tid & 31, w = tid >> 5;
    int wm = w >> 2, wn = w & 3;
    int m0 = blockIdx.y * 128, n0 = blockIdx.x * 128;

    int lrow = tid >> 1;
    int lcol = (tid & 1) * 16;
    const float* Ag = &g_hcatall[(size_t)(m0 + lrow) * KX + lcol];
    const float* Bg = Bw + (size_t)(n0 + lrow) * KX + lcol;

    float acc[4][4][4] = {};
    int qr = lane >> 2, qc = lane & 3;

    for (int k0 = 0; k0 < KX; k0 += OBK) {
        float4 a0 = *(const float4*)(Ag + k0);
        float4 a1 = *(const float4*)(Ag + k0 + 4);
        float4 a2 = *(const float4*)(Ag + k0 + 8);
        float4 a3 = *(const float4*)(Ag + k0 + 12);
        float4 b0 = *(const float4*)(Bg + k0);
        float4 b1 = *(const float4*)(Bg + k0 + 4);
        float4 b2 = *(const float4*)(Bg + k0 + 8);
        float4 b3 = *(const float4*)(Bg + k0 + 12);
        __syncthreads();
        {
            unsigned* ap = &As[lrow * SSTR + lcol];
            ap[0]  = f2tf32(a0.x); ap[1]  = f2tf32(a0.y);
            ap[2]  = f2tf32(a0.z); ap[3]  = f2tf32(a0.w);
            ap[4]  = f2tf32(a1.x); ap[5]  = f2tf32(a1.y);
            ap[6]  = f2tf32(a1.z); ap[7]  = f2tf32(a1.w);
            ap[8]  = f2tf32(a2.x); ap[9]  = f2tf32(a2.y);
            ap[10] = f2tf32(a2.z); ap[11] = f2tf32(a2.w);
            ap[12] = f2tf32(a3.x); ap[13] = f2tf32(a3.y);
            ap[14] = f2tf32(a3.z); ap[15] = f2tf32(a3.w);
            unsigned* bp = &Bs[lrow * SSTR + lcol];
            bp[0]  = f2tf32(b0.x); bp[1]  = f2tf32(b0.y);
            bp[2]  = f2tf32(b0.z); bp[3]  = f2tf32(b0.w);
            bp[4]  = f2tf32(b1.x); bp[5]  = f2tf32(b1.y);
            bp[6]  = f2tf32(b1.z); bp[7]  = f2tf32(b1.w);
            bp[8]  = f2tf32(b2.x); bp[9]  = f2tf32(b2.y);
            bp[10] = f2tf32(b2.z); bp[11] = f2tf32(b2.w);
            bp[12] = f2tf32(b3.x); bp[13] = f2tf32(b3.y);
            bp[14] = f2tf32(b3.z); bp[15] = f2tf32(b3.w);
        }
        __syncthreads();

        #pragma unroll
        for (int ks = 0; ks < OBK; ks += 8) {
            unsigned afr[4][4], bfr[4][2];
            #pragma unroll
            for (int mt = 0; mt < 4; mt++) {
                int r = wm * 64 + mt * 16 + qr;
                int c = ks + qc;
                afr[mt][0] = As[r * SSTR + c];
                afr[mt][1] = As[(r + 8) * SSTR + c];
                afr[mt][2] = As[r * SSTR + c + 4];
                afr[mt][3] = As[(r + 8) * SSTR + c + 4];
            }
            #pragma unroll
            for (int nt = 0; nt < 4; nt++) {
                int n = wn * 32 + nt * 8 + qr;
                int c = ks + qc;
                bfr[nt][0] = Bs[n * SSTR + c];
                bfr[nt][1] = Bs[n * SSTR + c + 4];
            }
            #pragma unroll
            for (int mt = 0; mt < 4; mt++)
                #pragma unroll
                for (int nt = 0; nt < 4; nt++)
                    mma_tf32(acc[mt][nt], afr[mt], bfr[nt]);
        }
    }

    #pragma unroll
    for (int mt = 0; mt < 4; mt++) {
        #pragma unroll
        for (int nt = 0; nt < 4; nt++) {
            int ncol = n0 + wn * 32 + nt * 8 + qc * 2;
            float bz0 = bias[ncol], bz1 = bias[ncol + 1];
            #pragma unroll
            for (int half = 0; half < 2; half++) {
                int r = m0 + wm * 64 + mt * 16 + qr + half * 8;
                int bidx = r & (B - 1);
                int tt = r >> 6;
                float* o = out + (size_t)bidx * T * V + (size_t)tt * V + ncol;
                float2 v = {acc[mt][nt][half * 2 + 0] + bz0,
                            acc[mt][nt][half * 2 + 1] + bz1};
                *(float2*)o = v;
            }
        }
    }
}

// -------------------- launch ------------------------------------------------
extern "C" void kernel_launch(void* const* d_in, const int* in_sizes, int n_in,
                              void* d_out, int out_size) {
    const float* enc   = (const float*)d_in[0];
    const int*   tgt   = (const int*)  d_in[1];
    const float* emb   = (const float*)d_in[2];
    const float* W_enc = (const float*)d_in[3];
    const float* W_dec = (const float*)d_in[4];
    const float* b_att = (const float*)d_in[5];
    const float* v_att = (const float*)d_in[6];
    const float* W_ih  = (const float*)d_in[7];
    const float* W_hh  = (const float*)d_in[8];
    const float* b_ih  = (const float*)d_in[9];
    const float* b_hh  = (const float*)d_in[10];
    const float* W_out = (const float*)d_in[11];
    const float* b_out = (const float*)d_in[12];
    float* out = (float*)d_out;

    float *p_encproj, *p_xe, *p_embpart;
    unsigned *p_WencT_hi, *p_WencT_lo, *p_We_hi, *p_We_lo;
    cudaGetSymbolAddress((void**)&p_encproj,  g_encproj);
    cudaGetSymbolAddress((void**)&p_xe,       g_xe);
    cudaGetSymbolAddress((void**)&p_embpart,  g_embpart);
    cudaGetSymbolAddress((void**)&p_WencT_hi, g_WencT_hi);
    cudaGetSymbolAddress((void**)&p_WencT_lo, g_WencT_lo);
    cudaGetSymbolAddress((void**)&p_We_hi,    g_We_hi);
    cudaGetSymbolAddress((void**)&p_We_lo,    g_We_lo);

    static bool attr_done = false;
    if (!attr_done) {
        cudaFuncSetAttribute(k_loop, cudaFuncAttributeMaxDynamicSharedMemorySize,
                             LOOP_SMEM_WORDS * 4);
        attr_done = true;
    }

    k_prep<<<512, 256>>>(W_enc, W_ih, W_hh, b_ih, b_hh, tgt, emb);

    // enc_proj[B*S, A] = enc @ W_enc (split-tf32)
    {
        dim3 grid(A_DIM / 128, (B * S) / 64, 1);
        k_mma_split<<<grid, 256>>>(enc, E, p_WencT_hi, p_WencT_lo, E,
                                   p_encproj, A_DIM, 0, E);
    }
    // embpart[T*B, G4] = xe @ We^T (split-tf32), once for all steps
    {
        dim3 grid(G4 / 128, (T * B) / 64, 1);
        k_mma_split<<<grid, 256>>>(p_xe, H, p_We_hi, p_We_lo, H,
                                   p_embpart, G4, 0, H);
    }

    // decode loop: persistent, 512 threads/block, 16-warp phases
    k_loop<<<NB, NT_LOOP, LOOP_SMEM_WORDS * 4>>>(enc, W_dec, b_att, v_att);

    // output projection for all timesteps
    {
        dim3 grid(V / 128, (T * B) / 128);
        k_out_mma<<<grid, 256>>>(W_out, b_out, out);
    }
}

// round 15
// speedup vs baseline: 1.1102x; 1.0018x over previous
#include <cuda_runtime.h>
#include <math.h>

// Problem constants
#define B     64
#define S     128
#define E     512
#define H     512
#define A_DIM 256
#define V     8192
#define T     32
#define KX    1024
#define KC    1024
#define G4    2048
#define KSPLIT 8
#define KCHUNK (KC / KSPLIT)   // 128
#define NB    128
#define NT_LOOP 512            // threads per k_loop block

// smem layout (words) for k_loop dynamic smem
#define WSTR  132
#define OFF_BH 0
#define OFF_BL (128 * WSTR)
#define OFF_AH (2 * 128 * WSTR)
#define OFF_AL (OFF_AH + 64 * WSTR)
#define LOOP_SMEM_WORDS (OFF_AL + 64 * WSTR)   // 50688 words = 202752 B

// -------------------- scratch (device globals) -----------------------------
__device__ float    g_encproj[B * S * A_DIM];
__device__ unsigned g_WencT_hi[A_DIM * E];
__device__ unsigned g_WencT_lo[A_DIM * E];
__device__ unsigned g_Wf_hi[G4 * KC];
__device__ unsigned g_Wf_lo[G4 * KC];
__device__ unsigned g_We_hi[G4 * H];
__device__ unsigned g_We_lo[G4 * H];
__device__ float    g_bf[G4];
__device__ float    g_xh[B * KC];            // [ctx | h_prev]
__device__ float    g_xe[T * B * H];
__device__ float    g_embpart[T * B * G4];
__device__ float    g_hcatall[T * B * KX];
__device__ float    g_c[B * H];
__device__ float    g_gpart[KSPLIT * B * G4];
__device__ float    g_dp2[2 * B * A_DIM];
__device__ float    g_scores[B * S];
__device__ unsigned g_bar_count = 0;
__device__ unsigned g_bar_phase = 0;

// -------------------- helpers ----------------------------------------------
__device__ __forceinline__ unsigned f2tf32(float x) {
    unsigned r;
    asm("cvt.rna.tf32.f32 %0, %1;" : "=r"(r) : "f"(x));
    return r;
}
__device__ __forceinline__ float tanh_fast(float x) {
    float y;
    asm("tanh.approx.f32 %0, %1;" : "=f"(y) : "f"(x));
    return y;
}
__device__ __forceinline__ float sigmoid_fast(float x) {
    return __fdividef(1.f, 1.f + __expf(-x));
}
__device__ __forceinline__ void mma_tf32(float* d, const unsigned* a, const unsigned* b) {
    asm("mma.sync.aligned.m16n8k8.row.col.f32.tf32.tf32.f32 "
        "{%0,%1,%2,%3}, {%4,%5,%6,%7}, {%8,%9}, {%0,%1,%2,%3};"
        : "+f"(d[0]), "+f"(d[1]), "+f"(d[2]), "+f"(d[3])
        : "r"(a[0]), "r"(a[1]), "r"(a[2]), "r"(a[3]), "r"(b[0]), "r"(b[1]));
}

#define CLUSTER_SYNC() do { \
    asm volatile("barrier.cluster.arrive.aligned;" ::: "memory"); \
    asm volatile("barrier.cluster.wait.aligned;" ::: "memory"); \
} while (0)

__device__ __forceinline__ void grid_barrier() {
    __syncthreads();
    if (threadIdx.x == 0) {
        __threadfence();
        unsigned gen = *((volatile unsigned*)&g_bar_phase);
        if (atomicAdd(&g_bar_count, 1u) == NB - 1) {
            *((volatile unsigned*)&g_bar_count) = 0;
            __threadfence();
            *((volatile unsigned*)&g_bar_phase) = gen + 1;
        } else {
            while (*((volatile unsigned*)&g_bar_phase) == gen) {}
        }
        __threadfence();
    }
    __syncthreads();
}

// -------------------- setup (incl. embedding gather) -----------------------
__global__ void k_prep(const float* __restrict__ W_enc,
                       const float* __restrict__ W_ih,
                       const float* __restrict__ W_hh,
                       const float* __restrict__ b_ih,
                       const float* __restrict__ b_hh,
                       const int* __restrict__ tgt,
                       const float* __restrict__ emb) {
    int stride = gridDim.x * blockDim.x;
    int tid0 = blockIdx.x * blockDim.x + threadIdx.x;
    for (int i = tid0; i < A_DIM * E; i += stride) {
        int a = i / E, e = i % E;
        float v = W_enc[e * A_DIM + a];
        unsigned hi = f2tf32(v);
        g_WencT_hi[i] = hi;
        g_WencT_lo[i] = f2tf32(v - __uint_as_float(hi));
    }
    for (int i = tid0; i < G4 * KC; i += stride) {
        int j = i / KC, k = i % KC;
        float v = (k < H) ? W_ih[j * KX + H + k] : W_hh[j * H + (k - H)];
        unsigned hi = f2tf32(v);
        g_Wf_hi[i] = hi;
        g_Wf_lo[i] = f2tf32(v - __uint_as_float(hi));
    }
    for (int i = tid0; i < G4 * H; i += stride) {
        int j = i / H, k = i % H;
        float v = W_ih[j * KX + k];
        unsigned hi = f2tf32(v);
        g_We_hi[i] = hi;
        g_We_lo[i] = f2tf32(v - __uint_as_float(hi));
    }
    for (int i = tid0; i < G4; i += stride) g_bf[i] = b_ih[i] + b_hh[i];
    for (int i = tid0; i < B * H; i += stride) {
        g_c[i] = 0.0f;
        int b = i / H, j = i % H;
        g_xh[b * KC + H + j] = 0.0f;
    }
    for (int i = tid0; i < T * B * H; i += stride) {
        int r = i >> 9, k = i & 511;
        int t = r >> 6, b = r & 63;
        int tok = (t == 0) ? 0 : tgt[b * T + t - 1];
        g_xe[i] = emb[(size_t)tok * H + k];
    }
}

// -------------------- split-TF32 GEMM, software-pipelined -------------------
#define MSTR 20
__global__ __launch_bounds__(256, 2)
void k_mma_split(const float* __restrict__ A, int lda,
                 const unsigned* __restrict__ Bhi,
                 const unsigned* __restrict__ Blo, int ldb,
                 float* __restrict__ C, int ldc, size_t czstride,
                 int kchunk) {
    __shared__ unsigned Ah[64 * MSTR], Al[64 * MSTR];
    __shared__ unsigned Bh[128 * MSTR], Bl[128 * MSTR];
    int tid = threadIdx.x;
    int lane = tid & 31, w = tid >> 5;
    int wm = w >> 2, wn = w & 3;
    int qr = lane >> 2, qc = lane & 3;
    int m0 = blockIdx.y * 64, n0 = blockIdx.x * 128;
    int kbase = blockIdx.z * kchunk;

    int ar = tid >> 2, ac = (tid & 3) * 4;
    const float* Ag = A + (size_t)(m0 + ar) * lda + kbase + ac;
    int br = tid >> 1, bc = (tid & 1) * 8;
    const unsigned* Bhg = Bhi + (size_t)(n0 + br) * ldb + kbase + bc;
    const unsigned* Blg = Blo + (size_t)(n0 + br) * ldb + kbase + bc;

    float acc[2][4][4] = {};
    int nk = kchunk >> 4;

    // prologue: load tile 0
    float4 av  = *(const float4*)(Ag);
    uint4 bh0  = *(const uint4*)(Bhg);
    uint4 bh1  = *(const uint4*)(Bhg + 4);
    uint4 bl0  = *(const uint4*)(Blg);
    uint4 bl1  = *(const uint4*)(Blg + 4);

    for (int kt = 0; kt < nk; kt++) {
        __syncthreads();
        {
            float a[4] = {av.x, av.y, av.z, av.w};
            #pragma unroll
            for (int i = 0; i < 4; i++) {
                unsigned hi = f2tf32(a[i]);
                Ah[ar * MSTR + ac + i] = hi;
                Al[ar * MSTR + ac + i] = f2tf32(a[i] - __uint_as_float(hi));
            }
            unsigned* bp = &Bh[br * MSTR + bc];
            bp[0] = bh0.x; bp[1] = bh0.y; bp[2] = bh0.z; bp[3] = bh0.w;
            bp[4] = bh1.x; bp[5] = bh1.y; bp[6] = bh1.z; bp[7] = bh1.w;
            unsigned* lp = &Bl[br * MSTR + bc];
            lp[0] = bl0.x; lp[1] = bl0.y; lp[2] = bl0.z; lp[3] = bl0.w;
            lp[4] = bl1.x; lp[5] = bl1.y; lp[6] = bl1.z; lp[7] = bl1.w;
        }
        __syncthreads();

        // prefetch next tile (overlaps with MMA loop below)
        int koff2 = ((kt + 1 < nk) ? (kt + 1) : kt) * 16;
        float4 av_n = *(const float4*)(Ag + koff2);
        uint4 bh0_n = *(const uint4*)(Bhg + koff2);
        uint4 bh1_n = *(const uint4*)(Bhg + koff2 + 4);
        uint4 bl0_n = *(const uint4*)(Blg + koff2);
        uint4 bl1_n = *(const uint4*)(Blg + koff2 + 4);

        #pragma unroll
        for (int ks = 0; ks < 16; ks += 8) {
            unsigned ah[2][4], al[2][4], bhf[4][2], blf[4][2];
            #pragma unroll
            for (int mt = 0; mt < 2; mt++) {
                int r = wm * 32 + mt * 16 + qr;
                int c = ks + qc;
                ah[mt][0] = Ah[r * MSTR + c];
                ah[mt][1] = Ah[(r + 8) * MSTR + c];
                ah[mt][2] = Ah[r * MSTR + c + 4];
                ah[mt][3] = Ah[(r + 8) * MSTR + c + 4];
                al[mt][0] = Al[r * MSTR + c];
                al[mt][1] = Al[(r + 8) * MSTR + c];
                al[mt][2] = Al[r * MSTR + c + 4];
                al[mt][3] = Al[(r + 8) * MSTR + c + 4];
            }
            #pragma unroll
            for (int nt = 0; nt < 4; nt++) {
                int n = wn * 32 + nt * 8 + qr;
                int c = ks + qc;
                bhf[nt][0] = Bh[n * MSTR + c];
                bhf[nt][1] = Bh[n * MSTR + c + 4];
                blf[nt][0] = Bl[n * MSTR + c];
                blf[nt][1] = Bl[n * MSTR + c + 4];
            }
            #pragma unroll
            for (int mt = 0; mt < 2; mt++)
                #pragma unroll
                for (int nt = 0; nt < 4; nt++) {
                    mma_tf32(acc[mt][nt], ah[mt], bhf[nt]);
                    mma_tf32(acc[mt][nt], ah[mt], blf[nt]);
                    mma_tf32(acc[mt][nt], al[mt], bhf[nt]);
                }
        }
        av = av_n; bh0 = bh0_n; bh1 = bh1_n; bl0 = bl0_n; bl1 = bl1_n;
    }

    float* Cp = C + (size_t)blockIdx.z * czstride;
    #pragma unroll
    for (int mt = 0; mt < 2; mt++)
        #pragma unroll
        for (int nt = 0; nt < 4; nt++) {
            int col = n0 + wn * 32 + nt * 8 + qc * 2;
            #pragma unroll
            for (int half = 0; half < 2; half++) {
                int row = m0 + wm * 32 + mt * 16 + qr + half * 8;
                float2 v = {acc[mt][nt][half * 2 + 0],
                            acc[mt][nt][half * 2 + 1]};
                *(float2*)&Cp[(size_t)row * ldc + col] = v;
            }
        }
}

// -------------------- persistent step loop (512 thr, 16-warp phases) --------
__global__ __launch_bounds__(NT_LOOP, 1) __cluster_dims__(2, 1, 1)
void k_loop(const float* __restrict__ enc, const float* __restrict__ W_dec,
            const float* __restrict__ b_att, const float* __restrict__ v_att) {
    extern __shared__ __align__(16) unsigned dyn[];
    int tid = threadIdx.x;
    int lane = tid & 31, warp = tid >> 5;
    int kc = blockIdx.x >> 4;
    int n0 = (blockIdx.x & 15) * 128;
    int kbase = kc * KCHUNK;
    int b = blockIdx.x >> 1;
    int rank = blockIdx.x & 1;
    int half_id = tid >> 8;
    int hid = tid & 255;

    unsigned* Bh = dyn + OFF_BH;
    unsigned* Bl = dyn + OFF_BL;
    unsigned* Ah = dyn + OFF_AH;
    unsigned* Al = dyn + OFF_AL;

    float* sh_h   = (float*)(dyn + OFF_AH);
    float* sh_dp  = sh_h + 256;
    float* sh_v   = sh_dp + 256;
    float* sh_sc  = sh_v + 256;
    float* sh_tmp = sh_sc + 128;
    float* sh_red = sh_tmp + 512;

    // one-time: pin gates weight tile (512 threads)
    {
        int r = tid >> 2;
        int cb = (tid & 3) * 32;
        const unsigned* hg = g_Wf_hi + (size_t)(n0 + r) * KC + kbase + cb;
        const unsigned* lg = g_Wf_lo + (size_t)(n0 + r) * KC + kbase + cb;
        #pragma unroll
        for (int j = 0; j < 8; j++) {
            uint4 hv = *(const uint4*)(hg + j * 4);
            uint4 lv = *(const uint4*)(lg + j * 4);
            unsigned* hp = &Bh[r * WSTR + cb + j * 4];
            unsigned* lp = &Bl[r * WSTR + cb + j * 4];
            hp[0] = hv.x; hp[1] = hv.y; hp[2] = hv.z; hp[3] = hv.w;
            lp[0] = lv.x; lp[1] = lv.y; lp[2] = lv.z; lp[3] = lv.w;
        }
    }
    __syncthreads();

    for (int t = 0; t <= T; t++) {
        // ---- P1: LSTM(t-1) ----
        if (t > 0) {
            int j = rank * 256 + hid;
            float gi, gf, gg, go;
            if (half_id == 0) {
                const float* ep = &g_embpart[(size_t)((t - 1) * B + b) * G4];
                gi = g_bf[j] + ep[j];
                gf = g_bf[j + H] + ep[j + H];
                gg = g_bf[j + 2 * H] + ep[j + 2 * H];
                go = g_bf[j + 3 * H] + ep[j + 3 * H];
            } else {
                gi = gf = gg = go = 0.f;
            }
            #pragma unroll
            for (int p = half_id * 4; p < half_id * 4 + 4; p++) {
                const float* gp = &g_gpart[(size_t)(p * B + b) * G4];
                gi += gp[j];         gf += gp[j + H];
                gg += gp[j + 2 * H]; go += gp[j + 3 * H];
            }
            sh_red[0 * 512 + tid] = gi;
            sh_red[1 * 512 + tid] = gf;
            sh_red[2 * 512 + tid] = gg;
            sh_red[3 * 512 + tid] = go;
            __syncthreads();
            if (half_id == 0) {
                float fi = sh_red[0 * 512 + hid] + sh_red[0 * 512 + 256 + hid];
                float ff = sh_red[1 * 512 + hid] + sh_red[1 * 512 + 256 + hid];
                float fg = sh_red[2 * 512 + hid] + sh_red[2 * 512 + 256 + hid];
                float fo = sh_red[3 * 512 + hid] + sh_red[3 * 512 + 256 + hid];
                float c = g_c[b * H + j];
                float cn = sigmoid_fast(ff) * c + sigmoid_fast(fi) * tanh_fast(fg);
                float hn = sigmoid_fast(fo) * tanh_fast(cn);
                g_c[b * H + j] = cn;
                sh_h[hid] = hn;
                g_xh[b * KC + H + j] = hn;
                g_hcatall[(size_t)((t - 1) * B + b) * KX + j] = hn;
            }
        } else {
            if (half_id == 0) sh_h[hid] = 0.f;
        }
        if (t == T) return;
        __syncthreads();

        // ---- P2: dp partial ----
        {
            const float* wd = W_dec + (size_t)(rank * 256 + half_id * 128) * A_DIM + hid;
            float a0 = 0.f, a1 = 0.f, a2 = 0.f, a3 = 0.f;
            const float* hh = sh_h + half_id * 128;
            #pragma unroll 4
            for (int e = 0; e < 128; e += 4) {
                a0 += hh[e]     * wd[(size_t)(e)     * A_DIM];
                a1 += hh[e + 1] * wd[(size_t)(e + 1) * A_DIM];
                a2 += hh[e + 2] * wd[(size_t)(e + 2) * A_DIM];
                a3 += hh[e + 3] * wd[(size_t)(e + 3) * A_DIM];
            }
            sh_tmp[tid] = (a0 + a1) + (a2 + a3);
            __syncthreads();
            if (half_id == 0)
                g_dp2[(rank * B + b) * A_DIM + hid] = sh_tmp[hid] + sh_tmp[hid + 256];
        }
        CLUSTER_SYNC();

        // ---- P3: scores ----
        {
            if (half_id == 0) {
                sh_dp[hid] = b_att[hid]
                           + g_dp2[(0 * B + b) * A_DIM + hid]
                           + g_dp2[(1 * B + b) * A_DIM + hid];
                sh_v[hid] = v_att[hid];
            }
            __syncthreads();
            for (int si = warp; si < 64; si += 16) {
                int s = rank * 64 + si;
                const float* ep2 = &g_encproj[((size_t)b * S + s) * A_DIM];
                float acc = 0.f;
                #pragma unroll
                for (int a = lane; a < A_DIM; a += 32)
                    acc += tanh_fast(ep2[a] + sh_dp[a]) * sh_v[a];
                #pragma unroll
                for (int o = 16; o; o >>= 1)
                    acc += __shfl_xor_sync(0xffffffffu, acc, o);
                if (lane == 0) g_scores[b * S + s] = acc;
            }
        }
        CLUSTER_SYNC();

        // ---- P4: softmax + ctx ----
        {
            if (tid < S) sh_sc[tid] = g_scores[b * S + tid];
            __syncthreads();
            if (warp == 0) {
                float v0 = sh_sc[lane], v1 = sh_sc[lane + 32];
                float v2 = sh_sc[lane + 64], v3 = sh_sc[lane + 96];
                float m = fmaxf(fmaxf(v0, v1), fmaxf(v2, v3));
                #pragma unroll
                for (int o = 16; o; o >>= 1)
                    m = fmaxf(m, __shfl_xor_sync(0xffffffffu, m, o));
                float e0 = __expf(v0 - m), e1 = __expf(v1 - m);
                float e2 = __expf(v2 - m), e3 = __expf(v3 - m);
                float sum = e0 + e1 + e2 + e3;
                #pragma unroll
                for (int o = 16; o; o >>= 1)
                    sum += __shfl_xor_sync(0xffffffffu, sum, o);
                float inv = __fdividef(1.f, sum);
                sh_sc[lane] = e0 * inv;        sh_sc[lane + 32] = e1 * inv;
                sh_sc[lane + 64] = e2 * inv;   sh_sc[lane + 96] = e3 * inv;
            }
            __syncthreads();

            int e = rank * 256 + hid;
            const float* eb = &enc[((size_t)b * S + half_id * 64) * E + e];
            const float* sc = sh_sc + half_id * 64;
            float a0 = 0.f, a1 = 0.f, a2 = 0.f, a3 = 0.f;
            #pragma unroll 4
            for (int s = 0; s < 64; s += 4) {
                a0 += sc[s]     * eb[(size_t)(s)     * E];
                a1 += sc[s + 1] * eb[(size_t)(s + 1) * E];
                a2 += sc[s + 2] * eb[(size_t)(s + 2) * E];
                a3 += sc[s + 3] * eb[(size_t)(s + 3) * E];
            }
            sh_tmp[tid] = (a0 + a1) + (a2 + a3);
            __syncthreads();
            if (half_id == 0) {
                float acc = sh_tmp[hid] + sh_tmp[hid + 256];
                g_xh[b * KC + e] = acc;
                g_hcatall[(size_t)(t * B + b) * KX + H + e] = acc;
            }
        }
        grid_barrier();

        // ---- P5: gates MMA, 16 warps ----
        {
            int wm = warp >> 2, wn = warp & 3;
            int qr = lane >> 2, qc = lane & 3;
            {
                int ar = tid >> 3;
                int acb = (tid & 7) * 16;
                const float* Ag = g_xh + ar * KC + kbase + acb;
                #pragma unroll
                for (int j = 0; j < 4; j++) {
                    float4 v = *(const float4*)(Ag + j * 4);
                    float a[4] = {v.x, v.y, v.z, v.w};
                    #pragma unroll
                    for (int i = 0; i < 4; i++) {
                        unsigned hi = f2tf32(a[i]);
                        Ah[ar * WSTR + acb + j * 4 + i] = hi;
                        Al[ar * WSTR + acb + j * 4 + i] =
                            f2tf32(a[i] - __uint_as_float(hi));
                    }
                }
            }
            __syncthreads();

            float acc[4][4] = {};
            #pragma unroll
            for (int ks = 0; ks < KCHUNK; ks += 8) {
                unsigned ah[4], al2[4], bhf[4][2], blf[4][2];
                int r = wm * 16 + qr;
                int c = ks + qc;
                ah[0] = Ah[r * WSTR + c];
                ah[1] = Ah[(r + 8) * WSTR + c];
                ah[2] = Ah[r * WSTR + c + 4];
                ah[3] = Ah[(r + 8) * WSTR + c + 4];
                al2[0] = Al[r * WSTR + c];
                al2[1] = Al[(r + 8) * WSTR + c];
                al2[2] = Al[r * WSTR + c + 4];
                al2[3] = Al[(r + 8) * WSTR + c + 4];
                #pragma unroll
                for (int nt = 0; nt < 4; nt++) {
                    int n = wn * 32 + nt * 8 + qr;
                    bhf[nt][0] = Bh[n * WSTR + c];
                    bhf[nt][1] = Bh[n * WSTR + c + 4];
                    blf[nt][0] = Bl[n * WSTR + c];
                    blf[nt][1] = Bl[n * WSTR + c + 4];
                }
                #pragma unroll
                for (int nt = 0; nt < 4; nt++) {
                    mma_tf32(acc[nt], ah, bhf[nt]);
                    mma_tf32(acc[nt], ah, blf[nt]);
                    mma_tf32(acc[nt], al2, bhf[nt]);
                }
            }

            float* Cp = g_gpart + (size_t)kc * B * G4;
            #pragma unroll
            for (int nt = 0; nt < 4; nt++) {
                int col = n0 + wn * 32 + nt * 8 + qc * 2;
                #pragma unroll
                for (int half = 0; half < 2; half++) {
                    int row = wm * 16 + qr + half * 8;
                    float2 v = {acc[nt][half * 2 + 0], acc[nt][half * 2 + 1]};
                    *(float2*)&Cp[(size_t)row * G4 + col] = v;
                }
            }
        }
        grid_barrier();
    }
}

// -------------------- TF32 output GEMM, software-pipelined (OBK=32) --------
#define OBK 32
#define SSTR 36
__global__ __launch_bounds__(256, 2)
void k_out_mma(const float* __restrict__ Bw, const float* __restrict__ bias,
               float* __restrict__ out) {
    __shared__ unsigned As[128 * SSTR];
    __shared__ unsigned Bs[128 * SSTR];
    int tid = threadIdx.x;
    int lane = tid & 31, w = tid >> 5;
    int wm = w >> 2, wn = w & 3;
    int m0 = blockIdx.y * 128, n0 = blockIdx.x * 128;

    int lrow = tid >> 1;
    int lcol = (tid & 1) * 16;
    const float* Ag = &g_hcatall[(size_t)(m0 + lrow) * KX + lcol];
    const float* Bg = Bw + (size_t)(n0 + lrow) * KX + lcol;

    float acc[4][4][4] = {};
    int qr = lane >> 2, qc = lane & 3;

    // prologue: load tile 0
    float4 a0 = *(const float4*)(Ag);
    float4 a1 = *(const float4*)(Ag + 4);
    float4 a2 = *(const float4*)(Ag + 8);
    float4 a3 = *(const float4*)(Ag + 12);
    float4 b0 = *(const float4*)(Bg);
    float4 b1 = *(const float4*)(Bg + 4);
    float4 b2 = *(const float4*)(Bg + 8);
    float4 b3 = *(const float4*)(Bg + 12);

    for (int k0 = 0; k0 < KX; k0 += OBK) {
        __syncthreads();
        {
            unsigned* ap = &As[lrow * SSTR + lcol];
            ap[0]  = f2tf32(a0.x); ap[1]  = f2tf32(a0.y);
            ap[2]  = f2tf32(a0.z); ap[3]  = f2tf32(a0.w);
            ap[4]  = f2tf32(a1.x); ap[5]  = f2tf32(a1.y);
            ap[6]  = f2tf32(a1.z); ap[7]  = f2tf32(a1.w);
            ap[8]  = f2tf32(a2.x); ap[9]  = f2tf32(a2.y);
            ap[10] = f2tf32(a2.z); ap[11] = f2tf32(a2.w);
            ap[12] = f2tf32(a3.x); ap[13] = f2tf32(a3.y);
            ap[14] = f2tf32(a3.z); ap[15] = f2tf32(a3.w);
            unsigned* bp = &Bs[lrow * SSTR + lcol];
            bp[0]  = f2tf32(b0.x); bp[1]  = f2tf32(b0.y);
            bp[2]  = f2tf32(b0.z); bp[3]  = f2tf32(b0.w);
            bp[4]  = f2tf32(b1.x); bp[5]  = f2tf32(b1.y);
            bp[6]  = f2tf32(b1.z); bp[7]  = f2tf32(b1.w);
            bp[8]  = f2tf32(b2.x); bp[9]  = f2tf32(b2.y);
            bp[10] = f2tf32(b2.z); bp[11] = f2tf32(b2.w);
            bp[12] = f2tf32(b3.x); bp[13] = f2tf32(b3.y);
            bp[14] = f2tf32(b3.z); bp[15] = f2tf32(b3.w);
        }
        __syncthreads();

        // prefetch next tile (overlaps with MMA loop)
        int kn = (k0 + OBK < KX) ? (k0 + OBK) : k0;
        float4 na0 = *(const float4*)(Ag + kn);
        float4 na1 = *(const float4*)(Ag + kn + 4);
        float4 na2 = *(const float4*)(Ag + kn + 8);
        float4 na3 = *(const float4*)(Ag + kn + 12);
        float4 nb0 = *(const float4*)(Bg + kn);
        float4 nb1 = *(const float4*)(Bg + kn + 4);
        float4 nb2 = *(const float4*)(Bg + kn + 8);
        float4 nb3 = *(const float4*)(Bg + kn + 12);

        #pragma unroll
        for (int ks = 0; ks < OBK; ks += 8) {
            unsigned afr[4][4], bfr[4][2];
            #pragma unroll
            for (int mt = 0; mt < 4; mt++) {
                int r = wm * 64 + mt * 16 + qr;
                int c = ks + qc;
                afr[mt][0] = As[r * SSTR + c];
                afr[mt][1] = As[(r + 8) * SSTR + c];
                afr[mt][2] = As[r * SSTR + c + 4];
                afr[mt][3] = As[(r + 8) * SSTR + c + 4];
            }
            #pragma unroll
            for (int nt = 0; nt < 4; nt++) {
                int n = wn * 32 + nt * 8 + qr;
                int c = ks + qc;
                bfr[nt][0] = Bs[n * SSTR + c];
                bfr[nt][1] = Bs[n * SSTR + c + 4];
            }
            #pragma unroll
            for (int mt = 0; mt < 4; mt++)
                #pragma unroll
                for (int nt = 0; nt < 4; nt++)
                    mma_tf32(acc[mt][nt], afr[mt], bfr[nt]);
        }
        a0 = na0; a1 = na1; a2 = na2; a3 = na3;
        b0 = nb0; b1 = nb1; b2 = nb2; b3 = nb3;
    }

    #pragma unroll
    for (int mt = 0; mt < 4; mt++) {
        #pragma unroll
        for (int nt = 0; nt < 4; nt++) {
            int ncol = n0 + wn * 32 + nt * 8 + qc * 2;
            float bz0 = bias[ncol], bz1 = bias[ncol + 1];
            #pragma unroll
            for (int half = 0; half < 2; half++) {
                int r = m0 + wm * 64 + mt * 16 + qr + half * 8;
                int bidx = r & (B - 1);
                int tt = r >> 6;
                float* o = out + (size_t)bidx * T * V + (size_t)tt * V + ncol;
                float2 v = {acc[mt][nt][half * 2 + 0] + bz0,
                            acc[mt][nt][half * 2 + 1] + bz1};
                *(float2*)o = v;
            }
        }
    }
}

// -------------------- launch ------------------------------------------------
extern "C" void kernel_launch(void* const* d_in, const int* in_sizes, int n_in,
                              void* d_out, int out_size) {
    const float* enc   = (const float*)d_in[0];
    const int*   tgt   = (const int*)  d_in[1];
    const float* emb   = (const float*)d_in[2];
    const float* W_enc = (const float*)d_in[3];
    const float* W_dec = (const float*)d_in[4];
    const float* b_att = (const float*)d_in[5];
    const float* v_att = (const float*)d_in[6];
    const float* W_ih  = (const float*)d_in[7];
    const float* W_hh  = (const float*)d_in[8];
    const float* b_ih  = (const float*)d_in[9];
    const float* b_hh  = (const float*)d_in[10];
    const float* W_out = (const float*)d_in[11];
    const float* b_out = (const float*)d_in[12];
    float* out = (float*)d_out;

    float *p_encproj, *p_xe, *p_embpart;
    unsigned *p_WencT_hi, *p_WencT_lo, *p_We_hi, *p_We_lo;
    cudaGetSymbolAddress((void**)&p_encproj,  g_encproj);
    cudaGetSymbolAddress((void**)&p_xe,       g_xe);
    cudaGetSymbolAddress((void**)&p_embpart,  g_embpart);
    cudaGetSymbolAddress((void**)&p_WencT_hi, g_WencT_hi);
    cudaGetSymbolAddress((void**)&p_WencT_lo, g_WencT_lo);
    cudaGetSymbolAddress((void**)&p_We_hi,    g_We_hi);
    cudaGetSymbolAddress((void**)&p_We_lo,    g_We_lo);

    static bool attr_done = false;
    if (!attr_done) {
        cudaFuncSetAttribute(k_loop, cudaFuncAttributeMaxDynamicSharedMemorySize,
                             LOOP_SMEM_WORDS * 4);
        attr_done = true;
    }

    k_prep<<<512, 256>>>(W_enc, W_ih, W_hh, b_ih, b_hh, tgt, emb);

    // enc_proj[B*S, A] = enc @ W_enc (split-tf32)
    {
        dim3 grid(A_DIM / 128, (B * S) / 64, 1);
        k_mma_split<<<grid, 256>>>(enc, E, p_WencT_hi, p_WencT_lo, E,
                                   p_encproj, A_DIM, 0, E);
    }
    // embpart[T*B, G4] = xe @ We^T (split-tf32), once for all steps
    {
        dim3 grid(G4 / 128, (T * B) / 64, 1);
        k_mma_split<<<grid, 256>>>(p_xe, H, p_We_hi, p_We_lo, H,
                                   p_embpart, G4, 0, H);
    }

    // decode loop: persistent, 512 threads/block, 16-warp phases
    k_loop<<<NB, NT_LOOP, LOOP_SMEM_WORDS * 4>>>(enc, W_dec, b_att, v_att);

    // output projection for all timesteps (pipelined)
    {
        dim3 grid(V / 128, (T * B) / 128);
        k_out_mma<<<grid, 256>>>(W_out, b_out, out);
    }
}

// round 16
// speedup vs baseline: 1.1277x; 1.0158x over previous
#include <cuda_runtime.h>
#include <math.h>

// Problem constants
#define B     64
#define S     128
#define E     512
#define H     512
#define A_DIM 256
#define V     8192
#define T     32
#define KX    1024
#define KC    1024
#define G4    2048
#define KSPLIT 8
#define KCHUNK (KC / KSPLIT)   // 128
#define NB    128
#define NT_LOOP 1024           // threads per k_loop block (32 warps)

// smem layout (words) for k_loop dynamic smem
#define WSTR  132
#define OFF_BH 0
#define OFF_BL (128 * WSTR)
#define OFF_AH (2 * 128 * WSTR)
#define OFF_AL (OFF_AH + 64 * WSTR)
#define LOOP_SMEM_WORDS (OFF_AL + 64 * WSTR)   // 50688 words = 202752 B

// -------------------- scratch (device globals) -----------------------------
__device__ float    g_encproj[B * S * A_DIM];
__device__ unsigned g_WencT_hi[A_DIM * E];
__device__ unsigned g_WencT_lo[A_DIM * E];
__device__ unsigned g_Wf_hi[G4 * KC];
__device__ unsigned g_Wf_lo[G4 * KC];
__device__ unsigned g_We_hi[G4 * H];
__device__ unsigned g_We_lo[G4 * H];
__device__ float    g_bf[G4];
__device__ float    g_xh[B * KC];            // [ctx | h_prev]
__device__ float    g_xe[T * B * H];
__device__ float    g_embpart[T * B * G4];
__device__ float    g_hcatall[T * B * KX];
__device__ float    g_c[B * H];
__device__ float    g_gpart[KSPLIT * B * G4];
__device__ float    g_dp2[2 * B * A_DIM];
__device__ float    g_scores[B * S];
__device__ unsigned g_bar_count = 0;
__device__ unsigned g_bar_phase = 0;

// -------------------- helpers ----------------------------------------------
__device__ __forceinline__ unsigned f2tf32(float x) {
    unsigned r;
    asm("cvt.rna.tf32.f32 %0, %1;" : "=r"(r) : "f"(x));
    return r;
}
__device__ __forceinline__ float tanh_fast(float x) {
    float y;
    asm("tanh.approx.f32 %0, %1;" : "=f"(y) : "f"(x));
    return y;
}
__device__ __forceinline__ float sigmoid_fast(float x) {
    return __fdividef(1.f, 1.f + __expf(-x));
}
__device__ __forceinline__ void mma_tf32(float* d, const unsigned* a, const unsigned* b) {
    asm("mma.sync.aligned.m16n8k8.row.col.f32.tf32.tf32.f32 "
        "{%0,%1,%2,%3}, {%4,%5,%6,%7}, {%8,%9}, {%0,%1,%2,%3};"
        : "+f"(d[0]), "+f"(d[1]), "+f"(d[2]), "+f"(d[3])
        : "r"(a[0]), "r"(a[1]), "r"(a[2]), "r"(a[3]), "r"(b[0]), "r"(b[1]));
}

#define CLUSTER_SYNC() do { \
    asm volatile("barrier.cluster.arrive.aligned;" ::: "memory"); \
    asm volatile("barrier.cluster.wait.aligned;" ::: "memory"); \
} while (0)

__device__ __forceinline__ void grid_barrier() {
    __syncthreads();
    if (threadIdx.x == 0) {
        __threadfence();
        unsigned gen = *((volatile unsigned*)&g_bar_phase);
        if (atomicAdd(&g_bar_count, 1u) == NB - 1) {
            *((volatile unsigned*)&g_bar_count) = 0;
            __threadfence();
            *((volatile unsigned*)&g_bar_phase) = gen + 1;
        } else {
            while (*((volatile unsigned*)&g_bar_phase) == gen) {}
        }
        __threadfence();
    }
    __syncthreads();
}

// -------------------- setup (incl. embedding gather) -----------------------
__global__ void k_prep(const float* __restrict__ W_enc,
                       const float* __restrict__ W_ih,
                       const float* __restrict__ W_hh,
                       const float* __restrict__ b_ih,
                       const float* __restrict__ b_hh,
                       const int* __restrict__ tgt,
                       const float* __restrict__ emb) {
    int stride = gridDim.x * blockDim.x;
    int tid0 = blockIdx.x * blockDim.x + threadIdx.x;
    for (int i = tid0; i < A_DIM * E; i += stride) {
        int a = i / E, e = i % E;
        float v = W_enc[e * A_DIM + a];
        unsigned hi = f2tf32(v);
        g_WencT_hi[i] = hi;
        g_WencT_lo[i] = f2tf32(v - __uint_as_float(hi));
    }
    for (int i = tid0; i < G4 * KC; i += stride) {
        int j = i / KC, k = i % KC;
        float v = (k < H) ? W_ih[j * KX + H + k] : W_hh[j * H + (k - H)];
        unsigned hi = f2tf32(v);
        g_Wf_hi[i] = hi;
        g_Wf_lo[i] = f2tf32(v - __uint_as_float(hi));
    }
    for (int i = tid0; i < G4 * H; i += stride) {
        int j = i / H, k = i % H;
        float v = W_ih[j * KX + k];
        unsigned hi = f2tf32(v);
        g_We_hi[i] = hi;
        g_We_lo[i] = f2tf32(v - __uint_as_float(hi));
    }
    for (int i = tid0; i < G4; i += stride) g_bf[i] = b_ih[i] + b_hh[i];
    for (int i = tid0; i < B * H; i += stride) {
        g_c[i] = 0.0f;
        int b = i / H, j = i % H;
        g_xh[b * KC + H + j] = 0.0f;
    }
    for (int i = tid0; i < T * B * H; i += stride) {
        int r = i >> 9, k = i & 511;
        int t = r >> 6, b = r & 63;
        int tok = (t == 0) ? 0 : tgt[b * T + t - 1];
        g_xe[i] = emb[(size_t)tok * H + k];
    }
}

// -------------------- split-TF32 GEMM, software-pipelined -------------------
#define MSTR 20
__global__ __launch_bounds__(256, 2)
void k_mma_split(const float* __restrict__ A, int lda,
                 const unsigned* __restrict__ Bhi,
                 const unsigned* __restrict__ Blo, int ldb,
                 float* __restrict__ C, int ldc, size_t czstride,
                 int kchunk) {
    __shared__ unsigned Ah[64 * MSTR], Al[64 * MSTR];
    __shared__ unsigned Bh[128 * MSTR], Bl[128 * MSTR];
    int tid = threadIdx.x;
    int lane = tid & 31, w = tid >> 5;
    int wm = w >> 2, wn = w & 3;
    int qr = lane >> 2, qc = lane & 3;
    int m0 = blockIdx.y * 64, n0 = blockIdx.x * 128;
    int kbase = blockIdx.z * kchunk;

    int ar = tid >> 2, ac = (tid & 3) * 4;
    const float* Ag = A + (size_t)(m0 + ar) * lda + kbase + ac;
    int br = tid >> 1, bc = (tid & 1) * 8;
    const unsigned* Bhg = Bhi + (size_t)(n0 + br) * ldb + kbase + bc;
    const unsigned* Blg = Blo + (size_t)(n0 + br) * ldb + kbase + bc;

    float acc[2][4][4] = {};
    int nk = kchunk >> 4;

    float4 av  = *(const float4*)(Ag);
    uint4 bh0  = *(const uint4*)(Bhg);
    uint4 bh1  = *(const uint4*)(Bhg + 4);
    uint4 bl0  = *(const uint4*)(Blg);
    uint4 bl1  = *(const uint4*)(Blg + 4);

    for (int kt = 0; kt < nk; kt++) {
        __syncthreads();
        {
            float a[4] = {av.x, av.y, av.z, av.w};
            #pragma unroll
            for (int i = 0; i < 4; i++) {
                unsigned hi = f2tf32(a[i]);
                Ah[ar * MSTR + ac + i] = hi;
                Al[ar * MSTR + ac + i] = f2tf32(a[i] - __uint_as_float(hi));
            }
            unsigned* bp = &Bh[br * MSTR + bc];
            bp[0] = bh0.x; bp[1] = bh0.y; bp[2] = bh0.z; bp[3] = bh0.w;
            bp[4] = bh1.x; bp[5] = bh1.y; bp[6] = bh1.z; bp[7] = bh1.w;
            unsigned* lp = &Bl[br * MSTR + bc];
            lp[0] = bl0.x; lp[1] = bl0.y; lp[2] = bl0.z; lp[3] = bl0.w;
            lp[4] = bl1.x; lp[5] = bl1.y; lp[6] = bl1.z; lp[7] = bl1.w;
        }
        __syncthreads();

        int koff2 = ((kt + 1 < nk) ? (kt + 1) : kt) * 16;
        float4 av_n = *(const float4*)(Ag + koff2);
        uint4 bh0_n = *(const uint4*)(Bhg + koff2);
        uint4 bh1_n = *(const uint4*)(Bhg + koff2 + 4);
        uint4 bl0_n = *(const uint4*)(Blg + koff2);
        uint4 bl1_n = *(const uint4*)(Blg + koff2 + 4);

        #pragma unroll
        for (int ks = 0; ks < 16; ks += 8) {
            unsigned ah[2][4], al[2][4], bhf[4][2], blf[4][2];
            #pragma unroll
            for (int mt = 0; mt < 2; mt++) {
                int r = wm * 32 + mt * 16 + qr;
                int c = ks + qc;
                ah[mt][0] = Ah[r * MSTR + c];
                ah[mt][1] = Ah[(r + 8) * MSTR + c];
                ah[mt][2] = Ah[r * MSTR + c + 4];
                ah[mt][3] = Ah[(r + 8) * MSTR + c + 4];
                al[mt][0] = Al[r * MSTR + c];
                al[mt][1] = Al[(r + 8) * MSTR + c];
                al[mt][2] = Al[r * MSTR + c + 4];
                al[mt][3] = Al[(r + 8) * MSTR + c + 4];
            }
            #pragma unroll
            for (int nt = 0; nt < 4; nt++) {
                int n = wn * 32 + nt * 8 + qr;
                int c = ks + qc;
                bhf[nt][0] = Bh[n * MSTR + c];
                bhf[nt][1] = Bh[n * MSTR + c + 4];
                blf[nt][0] = Bl[n * MSTR + c];
                blf[nt][1] = Bl[n * MSTR + c + 4];
            }
            #pragma unroll
            for (int mt = 0; mt < 2; mt++)
                #pragma unroll
                for (int nt = 0; nt < 4; nt++) {
                    mma_tf32(acc[mt][nt], ah[mt], bhf[nt]);
                    mma_tf32(acc[mt][nt], ah[mt], blf[nt]);
                    mma_tf32(acc[mt][nt], al[mt], bhf[nt]);
                }
        }
        av = av_n; bh0 = bh0_n; bh1 = bh1_n; bl0 = bl0_n; bl1 = bl1_n;
    }

    float* Cp = C + (size_t)blockIdx.z * czstride;
    #pragma unroll
    for (int mt = 0; mt < 2; mt++)
        #pragma unroll
        for (int nt = 0; nt < 4; nt++) {
            int col = n0 + wn * 32 + nt * 8 + qc * 2;
            #pragma unroll
            for (int half = 0; half < 2; half++) {
                int row = m0 + wm * 32 + mt * 16 + qr + half * 8;
                float2 v = {acc[mt][nt][half * 2 + 0],
                            acc[mt][nt][half * 2 + 1]};
                *(float2*)&Cp[(size_t)row * ldc + col] = v;
            }
        }
}

// -------------------- persistent step loop (1024 thr, 32-warp phases) -------
__global__ __launch_bounds__(NT_LOOP, 1) __cluster_dims__(2, 1, 1)
void k_loop(const float* __restrict__ enc, const float* __restrict__ W_dec,
            const float* __restrict__ b_att, const float* __restrict__ v_att) {
    extern __shared__ __align__(16) unsigned dyn[];
    int tid = threadIdx.x;
    int lane = tid & 31, warp = tid >> 5;
    int kc = blockIdx.x >> 4;
    int n0 = (blockIdx.x & 15) * 128;
    int kbase = kc * KCHUNK;
    int b = blockIdx.x >> 1;
    int rank = blockIdx.x & 1;
    int qid = tid >> 8;              // 0..3
    int hid = tid & 255;             // 0..255

    unsigned* Bh = dyn + OFF_BH;
    unsigned* Bl = dyn + OFF_BL;
    unsigned* Ah = dyn + OFF_AH;
    unsigned* Al = dyn + OFF_AL;

    // attention scratch aliases Ah/Al staging region (disjoint in time)
    float* sh_h   = (float*)(dyn + OFF_AH);  // 256
    float* sh_dp  = sh_h + 256;              // 256
    float* sh_v   = sh_dp + 256;             // 256
    float* sh_sc  = sh_v + 256;              // 128
    float* sh_tmp = sh_sc + 128;             // 1024
    float* sh_red = sh_tmp + 1024;           // 4*1024 = 4096

    // one-time: pin gates weight tile (1024 threads, 16 words each per array)
    {
        int r = tid >> 3;                 // 0..127
        int cb = (tid & 7) * 16;          // 0..112
        const unsigned* hg = g_Wf_hi + (size_t)(n0 + r) * KC + kbase + cb;
        const unsigned* lg = g_Wf_lo + (size_t)(n0 + r) * KC + kbase + cb;
        #pragma unroll
        for (int j = 0; j < 4; j++) {
            uint4 hv = *(const uint4*)(hg + j * 4);
            uint4 lv = *(const uint4*)(lg + j * 4);
            unsigned* hp = &Bh[r * WSTR + cb + j * 4];
            unsigned* lp = &Bl[r * WSTR + cb + j * 4];
            hp[0] = hv.x; hp[1] = hv.y; hp[2] = hv.z; hp[3] = hv.w;
            lp[0] = lv.x; lp[1] = lv.y; lp[2] = lv.z; lp[3] = lv.w;
        }
    }
    __syncthreads();

    for (int t = 0; t <= T; t++) {
        // ---- P1: LSTM(t-1); j = rank*256+hid; gpart sum split over quarters ----
        if (t > 0) {
            int j = rank * 256 + hid;
            float gi, gf, gg, go;
            if (qid == 0) {
                const float* ep = &g_embpart[(size_t)((t - 1) * B + b) * G4];
                gi = g_bf[j] + ep[j];
                gf = g_bf[j + H] + ep[j + H];
                gg = g_bf[j + 2 * H] + ep[j + 2 * H];
                go = g_bf[j + 3 * H] + ep[j + 3 * H];
            } else {
                gi = gf = gg = go = 0.f;
            }
            #pragma unroll
            for (int p = qid * 2; p < qid * 2 + 2; p++) {
                const float* gp = &g_gpart[(size_t)(p * B + b) * G4];
                gi += gp[j];         gf += gp[j + H];
                gg += gp[j + 2 * H]; go += gp[j + 3 * H];
            }
            sh_red[0 * 1024 + tid] = gi;
            sh_red[1 * 1024 + tid] = gf;
            sh_red[2 * 1024 + tid] = gg;
            sh_red[3 * 1024 + tid] = go;
            __syncthreads();
            if (qid == 0) {
                float fi = (sh_red[0 * 1024 + hid]       + sh_red[0 * 1024 + 256 + hid])
                         + (sh_red[0 * 1024 + 512 + hid] + sh_red[0 * 1024 + 768 + hid]);
                float ff = (sh_red[1 * 1024 + hid]       + sh_red[1 * 1024 + 256 + hid])
                         + (sh_red[1 * 1024 + 512 + hid] + sh_red[1 * 1024 + 768 + hid]);
                float fg = (sh_red[2 * 1024 + hid]       + sh_red[2 * 1024 + 256 + hid])
                         + (sh_red[2 * 1024 + 512 + hid] + sh_red[2 * 1024 + 768 + hid]);
                float fo = (sh_red[3 * 1024 + hid]       + sh_red[3 * 1024 + 256 + hid])
                         + (sh_red[3 * 1024 + 512 + hid] + sh_red[3 * 1024 + 768 + hid]);
                float c = g_c[b * H + j];
                float cn = sigmoid_fast(ff) * c + sigmoid_fast(fi) * tanh_fast(fg);
                float hn = sigmoid_fast(fo) * tanh_fast(cn);
                g_c[b * H + j] = cn;
                sh_h[hid] = hn;
                g_xh[b * KC + H + j] = hn;
                g_hcatall[(size_t)((t - 1) * B + b) * KX + j] = hn;
            }
        } else {
            if (qid == 0) sh_h[hid] = 0.f;
        }
        if (t == T) return;
        __syncthreads();

        // ---- P2: dp partial; a = hid, e-range split over quarters (64 each) ----
        {
            const float* wd = W_dec + (size_t)(rank * 256 + qid * 64) * A_DIM + hid;
            float a0 = 0.f, a1 = 0.f, a2 = 0.f, a3 = 0.f;
            const float* hh = sh_h + qid * 64;
            #pragma unroll 4
            for (int e = 0; e < 64; e += 4) {
                a0 += hh[e]     * wd[(size_t)(e)     * A_DIM];
                a1 += hh[e + 1] * wd[(size_t)(e + 1) * A_DIM];
                a2 += hh[e + 2] * wd[(size_t)(e + 2) * A_DIM];
                a3 += hh[e + 3] * wd[(size_t)(e + 3) * A_DIM];
            }
            sh_tmp[tid] = (a0 + a1) + (a2 + a3);
            __syncthreads();
            if (qid == 0)
                g_dp2[(rank * B + b) * A_DIM + hid] =
                    (sh_tmp[hid]       + sh_tmp[hid + 256])
                  + (sh_tmp[hid + 512] + sh_tmp[hid + 768]);
        }
        CLUSTER_SYNC();

        // ---- P3: scores; 32 warps, 2 s each ----
        {
            if (qid == 0) {
                sh_dp[hid] = b_att[hid]
                           + g_dp2[(0 * B + b) * A_DIM + hid]
                           + g_dp2[(1 * B + b) * A_DIM + hid];
                sh_v[hid] = v_att[hid];
            }
            __syncthreads();
            for (int si = warp; si < 64; si += 32) {
                int s = rank * 64 + si;
                const float* ep2 = &g_encproj[((size_t)b * S + s) * A_DIM];
                float acc = 0.f;
                #pragma unroll
                for (int a = lane; a < A_DIM; a += 32)
                    acc += tanh_fast(ep2[a] + sh_dp[a]) * sh_v[a];
                #pragma unroll
                for (int o = 16; o; o >>= 1)
                    acc += __shfl_xor_sync(0xffffffffu, acc, o);
                if (lane == 0) g_scores[b * S + s] = acc;
            }
        }
        CLUSTER_SYNC();

        // ---- P4: softmax (warp 0) + ctx (e=hid slice, s-range quarters) ----
        {
            if (tid < S) sh_sc[tid] = g_scores[b * S + tid];
            __syncthreads();
            if (warp == 0) {
                float v0 = sh_sc[lane], v1 = sh_sc[lane + 32];
                float v2 = sh_sc[lane + 64], v3 = sh_sc[lane + 96];
                float m = fmaxf(fmaxf(v0, v1), fmaxf(v2, v3));
                #pragma unroll
                for (int o = 16; o; o >>= 1)
                    m = fmaxf(m, __shfl_xor_sync(0xffffffffu, m, o));
                float e0 = __expf(v0 - m), e1 = __expf(v1 - m);
                float e2 = __expf(v2 - m), e3 = __expf(v3 - m);
                float sum = e0 + e1 + e2 + e3;
                #pragma unroll
                for (int o = 16; o; o >>= 1)
                    sum += __shfl_xor_sync(0xffffffffu, sum, o);
                float inv = __fdividef(1.f, sum);
                sh_sc[lane] = e0 * inv;        sh_sc[lane + 32] = e1 * inv;
                sh_sc[lane + 64] = e2 * inv;   sh_sc[lane + 96] = e3 * inv;
            }
            __syncthreads();

            int e = rank * 256 + hid;
            const float* eb = &enc[((size_t)b * S + qid * 32) * E + e];
            const float* sc = sh_sc + qid * 32;
            float a0 = 0.f, a1 = 0.f, a2 = 0.f, a3 = 0.f;
            #pragma unroll 4
            for (int s = 0; s < 32; s += 4) {
                a0 += sc[s]     * eb[(size_t)(s)     * E];
                a1 += sc[s + 1] * eb[(size_t)(s + 1) * E];
                a2 += sc[s + 2] * eb[(size_t)(s + 2) * E];
                a3 += sc[s + 3] * eb[(size_t)(s + 3) * E];
            }
            sh_tmp[tid] = (a0 + a1) + (a2 + a3);
            __syncthreads();
            if (qid == 0) {
                float acc = (sh_tmp[hid]       + sh_tmp[hid + 256])
                          + (sh_tmp[hid + 512] + sh_tmp[hid + 768]);
                g_xh[b * KC + e] = acc;
                g_hcatall[(size_t)(t * B + b) * KX + H + e] = acc;
            }
        }
        grid_barrier();

        // ---- P5: gates MMA, 32 warps (warp tile 16 x 16) ----
        {
            int wm = warp >> 3, wn = warp & 7;     // 4(m) x 8(n) warp grid
            int qr = lane >> 2, qc = lane & 3;

            // stage A tile (64 x 128): 1024 threads, 8 elems each
            {
                int ar = tid >> 4;                 // 0..63
                int acb = (tid & 15) * 8;          // 0..120
                const float* Ag = g_xh + ar * KC + kbase + acb;
                #pragma unroll
                for (int j = 0; j < 2; j++) {
                    float4 v = *(const float4*)(Ag + j * 4);
                    float a[4] = {v.x, v.y, v.z, v.w};
                    #pragma unroll
                    for (int i = 0; i < 4; i++) {
                        unsigned hi = f2tf32(a[i]);
                        Ah[ar * WSTR + acb + j * 4 + i] = hi;
                        Al[ar * WSTR + acb + j * 4 + i] =
                            f2tf32(a[i] - __uint_as_float(hi));
                    }
                }
            }
            __syncthreads();

            float acc[2][4] = {};
            #pragma unroll
            for (int ks = 0; ks < KCHUNK; ks += 8) {
                unsigned ah[4], al2[4], bhf[2][2], blf[2][2];
                int r = wm * 16 + qr;
                int c = ks + qc;
                ah[0] = Ah[r * WSTR + c];
                ah[1] = Ah[(r + 8) * WSTR + c];
                ah[2] = Ah[r * WSTR + c + 4];
                ah[3] = Ah[(r + 8) * WSTR + c + 4];
                al2[0] = Al[r * WSTR + c];
                al2[1] = Al[(r + 8) * WSTR + c];
                al2[2] = Al[r * WSTR + c + 4];
                al2[3] = Al[(r + 8) * WSTR + c + 4];
                #pragma unroll
                for (int nt = 0; nt < 2; nt++) {
                    int n = wn * 16 + nt * 8 + qr;
                    bhf[nt][0] = Bh[n * WSTR + c];
                    bhf[nt][1] = Bh[n * WSTR + c + 4];
                    blf[nt][0] = Bl[n * WSTR + c];
                    blf[nt][1] = Bl[n * WSTR + c + 4];
                }
                #pragma unroll
                for (int nt = 0; nt < 2; nt++) {
                    mma_tf32(acc[nt], ah, bhf[nt]);
                    mma_tf32(acc[nt], ah, blf[nt]);
                    mma_tf32(acc[nt], al2, bhf[nt]);
                }
            }

            float* Cp = g_gpart + (size_t)kc * B * G4;
            #pragma unroll
            for (int nt = 0; nt < 2; nt++) {
                int col = n0 + wn * 16 + nt * 8 + qc * 2;
                #pragma unroll
                for (int half = 0; half < 2; half++) {
                    int row = wm * 16 + qr + half * 8;
                    float2 v = {acc[nt][half * 2 + 0], acc[nt][half * 2 + 1]};
                    *(float2*)&Cp[(size_t)row * G4 + col] = v;
                }
            }
        }
        grid_barrier();
    }
}

// -------------------- TF32 output GEMM, software-pipelined (OBK=32) --------
#define OBK 32
#define SSTR 36
__global__ __launch_bounds__(256, 2)
void k_out_mma(const float* __restrict__ Bw, const float* __restrict__ bias,
               float* __restrict__ out) {
    __shared__ unsigned As[128 * SSTR];
    __shared__ unsigned Bs[128 * SSTR];
    int tid = threadIdx.x;
    int lane = tid & 31, w = tid >> 5;
    int wm = w >> 2, wn = w & 3;
    int m0 = blockIdx.y * 128, n0 = blockIdx.x * 128;

    int lrow = tid >> 1;
    int lcol = (tid & 1) * 16;
    const float* Ag = &g_hcatall[(size_t)(m0 + lrow) * KX + lcol];
    const float* Bg = Bw + (size_t)(n0 + lrow) * KX + lcol;

    float acc[4][4][4] = {};
    int qr = lane >> 2, qc = lane & 3;

    float4 a0 = *(const float4*)(Ag);
    float4 a1 = *(const float4*)(Ag + 4);
    float4 a2 = *(const float4*)(Ag + 8);
    float4 a3 = *(const float4*)(Ag + 12);
    float4 b0 = *(const float4*)(Bg);
    float4 b1 = *(const float4*)(Bg + 4);
    float4 b2 = *(const float4*)(Bg + 8);
    float4 b3 = *(const float4*)(Bg + 12);

    for (int k0 = 0; k0 < KX; k0 += OBK) {
        __syncthreads();
        {
            unsigned* ap = &As[lrow * SSTR + lcol];
            ap[0]  = f2tf32(a0.x); ap[1]  = f2tf32(a0.y);
            ap[2]  = f2tf32(a0.z); ap[3]  = f2tf32(a0.w);
            ap[4]  = f2tf32(a1.x); ap[5]  = f2tf32(a1.y);
            ap[6]  = f2tf32(a1.z); ap[7]  = f2tf32(a1.w);
            ap[8]  = f2tf32(a2.x); ap[9]  = f2tf32(a2.y);
            ap[10] = f2tf32(a2.z); ap[11] = f2tf32(a2.w);
            ap[12] = f2tf32(a3.x); ap[13] = f2tf32(a3.y);
            ap[14] = f2tf32(a3.z); ap[15] = f2tf32(a3.w);
            unsigned* bp = &Bs[lrow * SSTR + lcol];
            bp[0]  = f2tf32(b0.x); bp[1]  = f2tf32(b0.y);
            bp[2]  = f2tf32(b0.z); bp[3]  = f2tf32(b0.w);
            bp[4]  = f2tf32(b1.x); bp[5]  = f2tf32(b1.y);
            bp[6]  = f2tf32(b1.z); bp[7]  = f2tf32(b1.w);
            bp[8]  = f2tf32(b2.x); bp[9]  = f2tf32(b2.y);
            bp[10] = f2tf32(b2.z); bp[11] = f2tf32(b2.w);
            bp[12] = f2tf32(b3.x); bp[13] = f2tf32(b3.y);
            bp[14] = f2tf32(b3.z); bp[15] = f2tf32(b3.w);
        }
        __syncthreads();

        int kn = (k0 + OBK < KX) ? (k0 + OBK) : k0;
        float4 na0 = *(const float4*)(Ag + kn);
        float4 na1 = *(const float4*)(Ag + kn + 4);
        float4 na2 = *(const float4*)(Ag + kn + 8);
        float4 na3 = *(const float4*)(Ag + kn + 12);
        float4 nb0 = *(const float4*)(Bg + kn);
        float4 nb1 = *(const float4*)(Bg + kn + 4);
        float4 nb2 = *(const float4*)(Bg + kn + 8);
        float4 nb3 = *(const float4*)(Bg + kn + 12);

        #pragma unroll
        for (int ks = 0; ks < OBK; ks += 8) {
            unsigned afr[4][4], bfr[4][2];
            #pragma unroll
            for (int mt = 0; mt < 4; mt++) {
                int r = wm * 64 + mt * 16 + qr;
                int c = ks + qc;
                afr[mt][0] = As[r * SSTR + c];
                afr[mt][1] = As[(r + 8) * SSTR + c];
                afr[mt][2] = As[r * SSTR + c + 4];
                afr[mt][3] = As[(r + 8) * SSTR + c + 4];
            }
            #pragma unroll
            for (int nt = 0; nt < 4; nt++) {
                int n = wn * 32 + nt * 8 + qr;
                int c = ks + qc;
                bfr[nt][0] = Bs[n * SSTR + c];
                bfr[nt][1] = Bs[n * SSTR + c + 4];
            }
            #pragma unroll
            for (int mt = 0; mt < 4; mt++)
                #pragma unroll
                for (int nt = 0; nt < 4; nt++)
                    mma_tf32(acc[mt][nt], afr[mt], bfr[nt]);
        }
        a0 = na0; a1 = na1; a2 = na2; a3 = na3;
        b0 = nb0; b1 = nb1; b2 = nb2; b3 = nb3;
    }

    #pragma unroll
    for (int mt = 0; mt < 4; mt++) {
        #pragma unroll
        for (int nt = 0; nt < 4; nt++) {
            int ncol = n0 + wn * 32 + nt * 8 + qc * 2;
            float bz0 = bias[ncol], bz1 = bias[ncol + 1];
            #pragma unroll
            for (int half = 0; half < 2; half++) {
                int r = m0 + wm * 64 + mt * 16 + qr + half * 8;
                int bidx = r & (B - 1);
                int tt = r >> 6;
                float* o = out + (size_t)bidx * T * V + (size_t)tt * V + ncol;
                float2 v = {acc[mt][nt][half * 2 + 0] + bz0,
                            acc[mt][nt][half * 2 + 1] + bz1};
                *(float2*)o = v;
            }
        }
    }
}

// -------------------- launch ------------------------------------------------
extern "C" void kernel_launch(void* const* d_in, const int* in_sizes, int n_in,
                              void* d_out, int out_size) {
    const float* enc   = (const float*)d_in[0];
    const int*   tgt   = (const int*)  d_in[1];
    const float* emb   = (const float*)d_in[2];
    const float* W_enc = (const float*)d_in[3];
    const float* W_dec = (const float*)d_in[4];
    const float* b_att = (const float*)d_in[5];
    const float* v_att = (const float*)d_in[6];
    const float* W_ih  = (const float*)d_in[7];
    const float* W_hh  = (const float*)d_in[8];
    const float* b_ih  = (const float*)d_in[9];
    const float* b_hh  = (const float*)d_in[10];
    const float* W_out = (const float*)d_in[11];
    const float* b_out = (const float*)d_in[12];
    float* out = (float*)d_out;

    float *p_encproj, *p_xe, *p_embpart;
    unsigned *p_WencT_hi, *p_WencT_lo, *p_We_hi, *p_We_lo;
    cudaGetSymbolAddress((void**)&p_encproj,  g_encproj);
    cudaGetSymbolAddress((void**)&p_xe,       g_xe);
    cudaGetSymbolAddress((void**)&p_embpart,  g_embpart);
    cudaGetSymbolAddress((void**)&p_WencT_hi, g_WencT_hi);
    cudaGetSymbolAddress((void**)&p_WencT_lo, g_WencT_lo);
    cudaGetSymbolAddress((void**)&p_We_hi,    g_We_hi);
    cudaGetSymbolAddress((void**)&p_We_lo,    g_We_lo);

    static bool attr_done = false;
    if (!attr_done) {
        cudaFuncSetAttribute(k_loop, cudaFuncAttributeMaxDynamicSharedMemorySize,
                             LOOP_SMEM_WORDS * 4);
        attr_done = true;
    }

    k_prep<<<512, 256>>>(W_enc, W_ih, W_hh, b_ih, b_hh, tgt, emb);

    // enc_proj[B*S, A] = enc @ W_enc (split-tf32)
    {
        dim3 grid(A_DIM / 128, (B * S) / 64, 1);
        k_mma_split<<<grid, 256>>>(enc, E, p_WencT_hi, p_WencT_lo, E,
                                   p_encproj, A_DIM, 0, E);
    }
    // embpart[T*B, G4] = xe @ We^T (split-tf32), once for all steps
    {
        dim3 grid(G4 / 128, (T * B) / 64, 1);
        k_mma_split<<<grid, 256>>>(p_xe, H, p_We_hi, p_We_lo, H,
                                   p_embpart, G4, 0, H);
    }

    // decode loop: persistent, 1024 threads/block, 32-warp phases
    k_loop<<<NB, NT_LOOP, LOOP_SMEM_WORDS * 4>>>(enc, W_dec, b_att, v_att);

    // output projection for all timesteps (pipelined)
    {
        dim3 grid(V / 128, (T * B) / 128);
        k_out_mma<<<grid, 256>>>(W_out, b_out, out);
    }
}